// round 12
// baseline (speedup 1.0000x reference)
#include <cuda_runtime.h>
#include <cuda_fp16.h>
#include <mma.h>
#include <math.h>
#include <stdint.h>

#define BATCH 512
#define SEQ   200
#define FIN   32
#define EMB   128
#define HID   128
#define GATE  512            // 4*HID
#define NL    2
#define MROWS (BATCH*SEQ)    // 102400
#define KDIM  128

// ---------------- scratch (__device__ globals) ----------------
__device__ __half g_A [(size_t)MROWS*NL*GATE];          // LSTM input projections (fp16), [t][b] rows
__device__ float  g_Mb[(size_t)MROWS*SEQ];              // fc2 out [b][n][n']
__device__ float4 g_Wt4[NL*(HID/4)*GATE];               // Whh transposed k-major
__device__ float  g_blstm[NL*GATE];                     // b_ih + b_hh
__device__ float  g_zero[NL*GATE];                      // zero bias for gemm3

// fp16 operands for tensor GEMMs (lo-parts only where actually consumed)
__device__ __half g_xsh[(size_t)MROWS*EMB];                             // [t][b] rows
__device__ __half g_wihh[NL*GATE*EMB],      g_wihl[NL*GATE*EMB];
__device__ __half g_wf1h[EMB*HID],          g_wf1l[EMB*HID];
__device__ __half g_wf2h[SEQ*EMB],          g_wf2l[SEQ*EMB];
__device__ __half g_hsh[(size_t)MROWS*HID];                             // [b][t] rows
__device__ __half g_f1h[(size_t)MROWS*EMB], g_f1l[(size_t)MROWS*EMB];

__device__ __forceinline__ void split2h(float v, __half& h, __half& l) {
    h = __float2half_rn(v);
    l = __float2half_rn(v - __half2float(h));
}

// packed fp32x2 FMA (embed + lstm scalar paths)
union f4u { float4 f4; unsigned long long u[2]; };
__device__ __forceinline__ void ffma2(unsigned long long& d,
                                      unsigned long long a,
                                      unsigned long long b) {
    asm("fma.rn.f32x2 %0, %1, %2, %0;" : "+l"(d) : "l"(a), "l"(b));
}
__device__ __forceinline__ float hadd2(unsigned long long v) {
    union { unsigned long long u; float2 f; } c; c.u = v;
    return c.f.x + c.f.y;
}

// fast activations (MUFU-based; lstm only — low volume there)
__device__ __forceinline__ float fsig(float x)  { return __fdividef(1.f, 1.f + __expf(-x)); }
__device__ __forceinline__ float ftanh(float x) { return __fdividef(2.f, 1.f + __expf(-2.f*x)) - 1.f; }

// polynomial exp on FMA pipe (avoids MUFU bottleneck; rel err ~1e-6)
__device__ __forceinline__ float fexp(float x) {
    float t = x * 1.4426950408889634f;     // x * log2(e)
    float r = rintf(t);
    float y = (t - r) * 0.6931471805599453f;
    float p = 0.008333333f;
    p = fmaf(p, y, 0.041666667f);
    p = fmaf(p, y, 0.16666667f);
    p = fmaf(p, y, 0.5f);
    p = fmaf(p, y, 1.0f);
    p = fmaf(p, y, 1.0f);
    float s = __int_as_float(((int)r + 127) << 23);
    return p * s;
}

// ---------------- prep: Whh transpose, bias sums, weight fp16 splits ----------------
__global__ void prep_kernel(const float* __restrict__ w_hh,
                            const float* __restrict__ b_ih,
                            const float* __restrict__ b_hh,
                            const float* __restrict__ w_ih,
                            const float* __restrict__ w_fc1,
                            const float* __restrict__ w_fc2) {
    int idx = blockIdx.x*blockDim.x + threadIdx.x;
    int stride = gridDim.x*blockDim.x;
    const int tot = NL*(HID/4)*GATE;
    for (int q = idx; q < tot; q += stride) {
        int j  = q % GATE;
        int k4 = (q / GATE) % (HID/4);
        int l  = q / (GATE*(HID/4));
        const float* wr = w_hh + ((size_t)(l*GATE + j))*HID + k4*4;
        g_Wt4[q] = make_float4(wr[0], wr[1], wr[2], wr[3]);
    }
    for (int q = idx; q < NL*GATE; q += stride) {
        g_blstm[q] = b_ih[q] + b_hh[q];
        g_zero[q]  = 0.f;
    }
    for (int q = idx; q < NL*GATE*EMB; q += stride) split2h(w_ih[q],  g_wihh[q], g_wihl[q]);
    for (int q = idx; q < EMB*HID;     q += stride) split2h(w_fc1[q], g_wf1h[q], g_wf1l[q]);
    for (int q = idx; q < SEQ*EMB;     q += stride) split2h(w_fc2[q], g_wf2h[q], g_wf2l[q]);
}

// ---------------- embed: e = leaky(x @ w_emb^T + b) -> fp16 hi, rows [t*BATCH+b] -------
__global__ __launch_bounds__(256) void embed_kernel(
    const float* __restrict__ A, const float* __restrict__ B,
    const float* __restrict__ bias,
    __half* __restrict__ outh)
{
    const int K = FIN, K4 = FIN/4, N = EMB;
    extern __shared__ float4 sm4[];
    float4* As4 = sm4;
    float4* Bs4 = sm4 + 128*K4;

    const int m0 = blockIdx.y * 128;
    const int tid = threadIdx.x;

    for (int q = tid; q < 128*K4; q += 256) {
        int row = q / K4, k4 = q % K4;
        As4[row*K4 + (k4 ^ ((row>>3)&7))] = *(const float4*)(A + ((size_t)(m0+row))*K + (k4<<2));
    }
    for (int q = tid; q < 128*K4; q += 256) {
        int row = q / K4, k4 = q % K4;
        Bs4[row*K4 + (k4 ^ ((row>>3)&7))] = *(const float4*)(B + ((size_t)row)*K + (k4<<2));
    }
    __syncthreads();

    const int tx = tid & 15, ty = tid >> 4;
    const int swa = ty & 7, swb = tx & 7;

    unsigned long long acc[8][8];
    #pragma unroll
    for (int i = 0; i < 8; i++)
        #pragma unroll
        for (int j = 0; j < 8; j++) acc[i][j] = 0ULL;

    for (int k4 = 0; k4 < K4; k4++) {
        int ka = (k4 ^ swa) & (K4-1), kb = (k4 ^ swb) & (K4-1);
        f4u av[8];
        #pragma unroll
        for (int ii = 0; ii < 8; ii++) av[ii].f4 = As4[(ty*8+ii)*K4 + ka];
        #pragma unroll
        for (int jj = 0; jj < 8; jj++) {
            f4u bv; bv.f4 = Bs4[(tx*8+jj)*K4 + kb];
            #pragma unroll
            for (int ii = 0; ii < 8; ii++) {
                ffma2(acc[ii][jj], av[ii].u[0], bv.u[0]);
                ffma2(acc[ii][jj], av[ii].u[1], bv.u[1]);
            }
        }
    }

    #pragma unroll
    for (int ii = 0; ii < 8; ii++) {
        int m = m0 + ty*8 + ii;
        int b = m / SEQ, t = m - b*SEQ;
        size_t orow = (size_t)t*BATCH + b;     // [t][b] row remap for gemm3/lstm locality
        union { unsigned short s[8]; uint4 v; } ph;
        #pragma unroll
        for (int jj = 0; jj < 8; jj++) {
            int n = tx*8 + jj;
            float v = hadd2(acc[ii][jj]) + bias[n];
            v = (v >= 0.f) ? v : 0.01f*v;
            ph.s[jj] = __half_as_ushort(__float2half_rn(v));
        }
        *(uint4*)(outh + orow*N + tx*8) = ph.v;
    }
}

// ---------------- tgemm2: C = act(A @ (Bh+Bl)^T + bias), 2-product fp16 ---------------
// 3 smem tiles (102KB) -> 2 CTAs/SM. C output is fp16 (gemm3 path) or hi/lo split (fc1).
__global__ __launch_bounds__(256, 2) void tgemm2_kernel(
    const __half* __restrict__ Ah,
    const __half* __restrict__ Bh, const __half* __restrict__ Bl,
    const float* __restrict__ bias, __half* __restrict__ C,
    __half* __restrict__ Ch, __half* __restrict__ Cl,
    int Ntot, int ldC, int Brows, int act)
{
    using namespace nvcuda;
    const int LDT = 136;
    extern __shared__ __align__(32) char smem[];
    __half* sAh = (__half*)smem;
    __half* sBh = sAh + 128*LDT;
    __half* sBl = sBh + 128*LDT;

    const int tid = threadIdx.x;
    const int w = tid >> 5, lane = tid & 31;
    const int wm = w >> 1, wn = w & 1;          // 4x2 warp grid
    const int m0 = blockIdx.y * 128;
    const int n0 = blockIdx.x * 128;

    for (int q = tid; q < 128*16; q += 256) {
        int row = q >> 4, c = q & 15;
        uint4 va  = *(const uint4*)(Ah + (size_t)(m0+row)*KDIM + c*8);
        uint4 vb  = make_uint4(0u,0u,0u,0u), vbl = make_uint4(0u,0u,0u,0u);
        if (n0 + row < Brows) {
            vb  = *(const uint4*)(Bh + (size_t)(n0+row)*KDIM + c*8);
            vbl = *(const uint4*)(Bl + (size_t)(n0+row)*KDIM + c*8);
        }
        *(uint4*)(sAh + row*LDT + c*8) = va;
        *(uint4*)(sBh + row*LDT + c*8) = vb;
        *(uint4*)(sBl + row*LDT + c*8) = vbl;
    }
    __syncthreads();

    wmma::fragment<wmma::accumulator, 16, 16, 16, float> acc[2][4];
    #pragma unroll
    for (int ti = 0; ti < 2; ti++)
        #pragma unroll
        for (int tj = 0; tj < 4; tj++) wmma::fill_fragment(acc[ti][tj], 0.0f);

    #pragma unroll 2
    for (int ks = 0; ks < 8; ks++) {
        wmma::fragment<wmma::matrix_a, 16, 16, 16, __half, wmma::row_major> ah[2];
        #pragma unroll
        for (int ti = 0; ti < 2; ti++)
            wmma::load_matrix_sync(ah[ti], sAh + (wm*32 + ti*16)*LDT + ks*16, LDT);
        #pragma unroll
        for (int tj = 0; tj < 4; tj++) {
            int nrow = wn*64 + tj*16;
            wmma::fragment<wmma::matrix_b, 16, 16, 16, __half, wmma::col_major> bh, bl;
            wmma::load_matrix_sync(bh, sBh + nrow*LDT + ks*16, LDT);
            wmma::load_matrix_sync(bl, sBl + nrow*LDT + ks*16, LDT);
            #pragma unroll
            for (int ti = 0; ti < 2; ti++) {
                wmma::mma_sync(acc[ti][tj], ah[ti], bh, acc[ti][tj]);
                wmma::mma_sync(acc[ti][tj], ah[ti], bl, acc[ti][tj]);
            }
        }
    }
    __syncthreads();   // tiles dead; reuse smem front as per-warp stage

    float* stg = (float*)smem + w*16*20;
    const int r = lane >> 1, seg = lane & 1;
    #pragma unroll 1
    for (int ti = 0; ti < 2; ti++)
    #pragma unroll 1
    for (int tj = 0; tj < 4; tj++) {
        wmma::store_matrix_sync(stg, acc[ti][tj], 20, wmma::mem_row_major);
        __syncwarp();
        size_t orow = (size_t)(m0 + wm*32 + ti*16 + r);
        int nbase = n0 + wn*64 + tj*16 + seg*8;
        float v[8];
        #pragma unroll
        for (int i = 0; i < 8; i++) {
            int n = nbase + i;
            float t = stg[r*20 + seg*8 + i] + ((n < Ntot) ? bias[n] : 0.f);
            if (act) t = (t >= 0.f) ? t : 0.01f*t;
            v[i] = t;
        }
        if (C) {
            union { unsigned short s[8]; uint4 q; } pc;
            #pragma unroll
            for (int i = 0; i < 8; i++)
                pc.s[i] = __half_as_ushort(__float2half_rn(v[i]));
            if (nbase + 8 <= Ntot) {
                *(uint4*)(C + orow*ldC + nbase) = pc.q;
            } else {
                for (int i = 0; i < 8; i++)
                    if (nbase + i < Ntot) C[orow*ldC + nbase + i] = __float2half_rn(v[i]);
            }
        } else {
            union { unsigned short s[8]; uint4 q; } ph, pl;
            #pragma unroll
            for (int i = 0; i < 8; i++) {
                __half h, l; split2h(v[i], h, l);
                ph.s[i] = __half_as_ushort(h);
                pl.s[i] = __half_as_ushort(l);
            }
            *(uint4*)(Ch + orow*ldC + nbase) = ph.q;
            *(uint4*)(Cl + orow*ldC + nbase) = pl.q;
        }
        __syncwarp();
    }
}

// ---------------- tgemm3: C = (Ah+Al) @ (Bh+Bl)^T + bias (3-product, output path) -----
__global__ __launch_bounds__(256) void tgemm3_kernel(
    const __half* __restrict__ Ah, const __half* __restrict__ Al,
    const __half* __restrict__ Bh, const __half* __restrict__ Bl,
    const float* __restrict__ bias, float* __restrict__ C,
    int Ntot, int ldC, int Brows)
{
    using namespace nvcuda;
    const int LDT = 136;
    extern __shared__ __align__(32) char smem[];
    __half* sAh = (__half*)smem;
    __half* sAl = sAh + 128*LDT;
    __half* sBh = sAl + 128*LDT;
    __half* sBl = sBh + 128*LDT;

    const int tid = threadIdx.x;
    const int w = tid >> 5, lane = tid & 31;
    const int wm = w >> 1, wn = w & 1;
    const int m0 = blockIdx.y * 128;
    const int n0 = blockIdx.x * 128;

    for (int q = tid; q < 128*16; q += 256) {
        int row = q >> 4, c = q & 15;
        uint4 va  = *(const uint4*)(Ah + (size_t)(m0+row)*KDIM + c*8);
        uint4 val = *(const uint4*)(Al + (size_t)(m0+row)*KDIM + c*8);
        uint4 vb  = make_uint4(0u,0u,0u,0u), vbl = make_uint4(0u,0u,0u,0u);
        if (n0 + row < Brows) {
            vb  = *(const uint4*)(Bh + (size_t)(n0+row)*KDIM + c*8);
            vbl = *(const uint4*)(Bl + (size_t)(n0+row)*KDIM + c*8);
        }
        *(uint4*)(sAh + row*LDT + c*8) = va;
        *(uint4*)(sAl + row*LDT + c*8) = val;
        *(uint4*)(sBh + row*LDT + c*8) = vb;
        *(uint4*)(sBl + row*LDT + c*8) = vbl;
    }
    __syncthreads();

    wmma::fragment<wmma::accumulator, 16, 16, 16, float> acc[2][4];
    #pragma unroll
    for (int ti = 0; ti < 2; ti++)
        #pragma unroll
        for (int tj = 0; tj < 4; tj++) wmma::fill_fragment(acc[ti][tj], 0.0f);

    #pragma unroll 2
    for (int ks = 0; ks < 8; ks++) {
        wmma::fragment<wmma::matrix_a, 16, 16, 16, __half, wmma::row_major> ah[2], al[2];
        #pragma unroll
        for (int ti = 0; ti < 2; ti++) {
            int mrow = wm*32 + ti*16;
            wmma::load_matrix_sync(ah[ti], sAh + mrow*LDT + ks*16, LDT);
            wmma::load_matrix_sync(al[ti], sAl + mrow*LDT + ks*16, LDT);
        }
        wmma::fragment<wmma::matrix_b, 16, 16, 16, __half, wmma::col_major> bh[4], bl[4];
        #pragma unroll
        for (int tj = 0; tj < 4; tj++) {
            int nrow = wn*64 + tj*16;
            wmma::load_matrix_sync(bh[tj], sBh + nrow*LDT + ks*16, LDT);
            wmma::load_matrix_sync(bl[tj], sBl + nrow*LDT + ks*16, LDT);
        }
        #pragma unroll
        for (int ti = 0; ti < 2; ti++)
            #pragma unroll
            for (int tj = 0; tj < 4; tj++) {
                wmma::mma_sync(acc[ti][tj], ah[ti], bh[tj], acc[ti][tj]);
                wmma::mma_sync(acc[ti][tj], ah[ti], bl[tj], acc[ti][tj]);
                wmma::mma_sync(acc[ti][tj], al[ti], bh[tj], acc[ti][tj]);
            }
    }
    __syncthreads();

    float* stg = (float*)smem + w*16*20;
    const int r = lane >> 1, seg = lane & 1;
    #pragma unroll 1
    for (int ti = 0; ti < 2; ti++)
    #pragma unroll 1
    for (int tj = 0; tj < 4; tj++) {
        wmma::store_matrix_sync(stg, acc[ti][tj], 20, wmma::mem_row_major);
        __syncwarp();
        size_t orow = (size_t)(m0 + wm*32 + ti*16 + r);
        int nbase = n0 + wn*64 + tj*16 + seg*8;
        float v[8];
        #pragma unroll
        for (int i = 0; i < 8; i++) {
            int n = nbase + i;
            v[i] = stg[r*20 + seg*8 + i] + ((n < Ntot) ? bias[n] : 0.f);
        }
        if (nbase + 8 <= Ntot) {
            *(float4*)(C + orow*ldC + nbase)     = make_float4(v[0],v[1],v[2],v[3]);
            *(float4*)(C + orow*ldC + nbase + 4) = make_float4(v[4],v[5],v[6],v[7]);
        } else {
            for (int i = 0; i < 8; i++)
                if (nbase + i < Ntot) C[orow*ldC + nbase + i] = v[i];
        }
        __syncwarp();
    }
}

// ---------------- LSTM recurrence: 256 threads, 2 gates x 4 batches per thread --------
#define KC 16
#define KR 16
__global__ __launch_bounds__(256) void lstm_kernel(const __half* __restrict__ A,
                                                   __half* __restrict__ hsh)
{
    __shared__ float h_s[4][HID];
    __shared__ float c_s[4][HID];
    __shared__ float g_s[4][GATE];
    extern __shared__ float4 Wc[];   // KC*GATE float4 = 128 KB

    const int tid = threadIdx.x;
    const int j0 = tid, j1 = tid + 256;
    const int bb = blockIdx.x * 4;
    const int ub0 = tid >> 7,      uh = tid & 127;
    const int ub1 = 2 + (tid >> 7);

    h_s[ub0][uh] = 0.f; h_s[ub1][uh] = 0.f;
    c_s[ub0][uh] = 0.f; c_s[ub1][uh] = 0.f;

    for (int l = 0; l < NL; l++) {
        const float4* W = g_Wt4 + l*(HID/4)*GATE;
        const float bias0 = g_blstm[l*GATE + j0];
        const float bias1 = g_blstm[l*GATE + j1];
        __syncthreads();
        for (int q = tid; q < KC*GATE; q += 256) Wc[q] = W[q];
        f4u w0[KR], w1[KR];
        #pragma unroll
        for (int r = 0; r < KR; r++) {
            w0[r].f4 = W[(KC+r)*GATE + j0];
            w1[r].f4 = W[(KC+r)*GATE + j1];
        }
        __syncthreads();

        float a0[4], a1[4];
        {
            const __half* Ar = A + (size_t)bb*(NL*GATE) + l*GATE;
            #pragma unroll
            for (int b = 0; b < 4; b++) {
                a0[b] = __half2float(Ar[(size_t)b*(NL*GATE) + j0]);
                a1[b] = __half2float(Ar[(size_t)b*(NL*GATE) + j1]);
            }
        }

        for (int t = 0; t < SEQ; t++) {
            float na0[4], na1[4];
            if (t + 1 < SEQ) {
                const __half* Arn = A + ((size_t)((t+1)*BATCH + bb))*(NL*GATE) + l*GATE;
                #pragma unroll
                for (int b = 0; b < 4; b++) {
                    na0[b] = __half2float(Arn[(size_t)b*(NL*GATE) + j0]);
                    na1[b] = __half2float(Arn[(size_t)b*(NL*GATE) + j1]);
                }
            } else {
                #pragma unroll
                for (int b = 0; b < 4; b++) { na0[b] = 0.f; na1[b] = 0.f; }
            }

            unsigned long long s0[4] = {0,0,0,0}, s1[4] = {0,0,0,0};
            #pragma unroll
            for (int k4 = 0; k4 < KC; k4++) {
                f4u wv0; wv0.f4 = Wc[k4*GATE + j0];
                f4u wv1; wv1.f4 = Wc[k4*GATE + j1];
                #pragma unroll
                for (int b = 0; b < 4; b++) {
                    f4u hb; hb.f4 = *(const float4*)&h_s[b][k4<<2];
                    ffma2(s0[b], wv0.u[0], hb.u[0]); ffma2(s0[b], wv0.u[1], hb.u[1]);
                    ffma2(s1[b], wv1.u[0], hb.u[0]); ffma2(s1[b], wv1.u[1], hb.u[1]);
                }
            }
            #pragma unroll
            for (int r = 0; r < KR; r++) {
                int k4 = KC + r;
                #pragma unroll
                for (int b = 0; b < 4; b++) {
                    f4u hb; hb.f4 = *(const float4*)&h_s[b][k4<<2];
                    ffma2(s0[b], w0[r].u[0], hb.u[0]); ffma2(s0[b], w0[r].u[1], hb.u[1]);
                    ffma2(s1[b], w1[r].u[0], hb.u[0]); ffma2(s1[b], w1[r].u[1], hb.u[1]);
                }
            }
            #pragma unroll
            for (int b = 0; b < 4; b++) {
                g_s[b][j0] = hadd2(s0[b]) + a0[b] + bias0;
                g_s[b][j1] = hadd2(s1[b]) + a1[b] + bias1;
            }
            __syncthreads();

            #pragma unroll
            for (int p = 0; p < 2; p++) {
                int b = p ? ub1 : ub0;
                float ig = g_s[b][uh];
                float fg = g_s[b][HID   + uh];
                float gg = g_s[b][2*HID + uh];
                float og = g_s[b][3*HID + uh];
                float cc = fsig(fg)*c_s[b][uh] + fsig(ig)*ftanh(gg);
                float hh = fsig(og)*ftanh(cc);
                c_s[b][uh] = cc;
                h_s[b][uh] = hh;
                if (l == NL-1)
                    hsh[((size_t)(bb+b)*SEQ + t)*HID + uh] = __float2half_rn(hh);
            }
            __syncthreads();
            #pragma unroll
            for (int b = 0; b < 4; b++) { a0[b] = na0[b]; a1[b] = na1[b]; }
        }
    }
}

// ---------------- sinkhorn: fused row+col pass, poly exp, register col sums -----------
__global__ __launch_bounds__(512) void sinkhorn_kernel(const float* __restrict__ Min,
                                                       float* __restrict__ out)
{
    extern __shared__ float Ms[];               // SEQ*SEQ
    float* colpart = Ms + SEQ*SEQ;              // 16*SEQ
    float* colinv  = colpart + 16*SEQ;          // SEQ
    const int b = blockIdx.x, tid = threadIdx.x;
    const int lane = tid & 31, w = tid >> 5;    // 16 warps

    const float4* src = (const float4*)(Min + (size_t)b*SEQ*SEQ);
    for (int q = tid; q < SEQ*SEQ/4; q += 512) {
        float4 v = src[q];
        v.x = fexp(v.x); v.y = fexp(v.y); v.z = fexp(v.z); v.w = fexp(v.w);
        ((float4*)Ms)[q] = v;
    }
    if (tid < SEQ) colinv[tid] = 1.0f;
    __syncthreads();

    for (int it = 0; it < 5; it++) {
        float ci[7], cs[7];
        #pragma unroll
        for (int i = 0; i < 7; i++) {
            int c = lane + 32*i;
            ci[i] = (c < SEQ) ? colinv[c] : 0.f;
            cs[i] = 0.f;
        }
        for (int r = w; r < SEQ; r += 16) {
            float v[7]; float s = 0.f;
            #pragma unroll
            for (int i = 0; i < 7; i++) {
                int c = lane + 32*i;
                float x = (c < SEQ) ? Ms[r*SEQ + c] * ci[i] : 0.f;
                v[i] = x; s += x;
            }
            #pragma unroll
            for (int off = 16; off; off >>= 1) s += __shfl_xor_sync(0xffffffffu, s, off);
            float inv = 1.0f / s;
            #pragma unroll
            for (int i = 0; i < 7; i++) {
                int c = lane + 32*i;
                if (c < SEQ) {
                    float x = v[i] * inv;
                    Ms[r*SEQ + c] = x;
                    cs[i] += x;
                }
            }
        }
        #pragma unroll
        for (int i = 0; i < 7; i++) {
            int c = lane + 32*i;
            if (c < SEQ) colpart[w*SEQ + c] = cs[i];
        }
        __syncthreads();
        if (tid < SEQ) {
            float s = 0.f;
            #pragma unroll
            for (int k = 0; k < 16; k++) s += colpart[k*SEQ + tid];
            colinv[tid] = 1.0f / s;
        }
        __syncthreads();
    }

    float4* dst = (float4*)(out + (size_t)b*SEQ*SEQ);
    for (int q = tid; q < SEQ*SEQ/4; q += 512) {
        float4 v = ((const float4*)Ms)[q];
        int c0 = (q % (SEQ/4)) * 4;
        v.x *= colinv[c0]; v.y *= colinv[c0+1]; v.z *= colinv[c0+2]; v.w *= colinv[c0+3];
        dst[q] = v;
    }
}

// ---------------- launch ----------------
extern "C" void kernel_launch(void* const* d_in, const int* in_sizes, int n_in,
                              void* d_out, int out_size)
{
    const float* x     = (const float*)d_in[0];
    const float* w_emb = (const float*)d_in[1];
    const float* b_emb = (const float*)d_in[2];
    const float* w_ih  = (const float*)d_in[3];
    const float* w_hh  = (const float*)d_in[4];
    const float* b_ih  = (const float*)d_in[5];
    const float* b_hh  = (const float*)d_in[6];
    const float* w_fc1 = (const float*)d_in[7];
    const float* b_fc1 = (const float*)d_in[8];
    const float* w_fc2 = (const float*)d_in[9];
    const float* b_fc2 = (const float*)d_in[10];
    float* out = (float*)d_out;

    float *Mb, *zero;
    __half *Ab, *xsh,*wihh,*wihl,*wf1h,*wf1l,*wf2h,*wf2l,*hsh,*f1h,*f1l;
    cudaGetSymbolAddress((void**)&Ab,   g_A);
    cudaGetSymbolAddress((void**)&Mb,   g_Mb);
    cudaGetSymbolAddress((void**)&zero, g_zero);
    cudaGetSymbolAddress((void**)&xsh,  g_xsh);
    cudaGetSymbolAddress((void**)&wihh, g_wihh); cudaGetSymbolAddress((void**)&wihl, g_wihl);
    cudaGetSymbolAddress((void**)&wf1h, g_wf1h); cudaGetSymbolAddress((void**)&wf1l, g_wf1l);
    cudaGetSymbolAddress((void**)&wf2h, g_wf2h); cudaGetSymbolAddress((void**)&wf2l, g_wf2l);
    cudaGetSymbolAddress((void**)&hsh,  g_hsh);
    cudaGetSymbolAddress((void**)&f1h,  g_f1h);  cudaGetSymbolAddress((void**)&f1l, g_f1l);

    const int TG2_SMEM = 3*128*136*2;         // 104448 (3 tiles -> 2 CTAs/SM)
    const int TG3_SMEM = 4*128*136*2;         // 139264
    const int LS_SMEM  = KC*GATE*16;          // 131072
    const int SK_SMEM  = (SEQ*SEQ + 16*SEQ + SEQ)*4;   // 173600
    cudaFuncSetAttribute(tgemm2_kernel,   cudaFuncAttributeMaxDynamicSharedMemorySize, TG2_SMEM);
    cudaFuncSetAttribute(tgemm3_kernel,   cudaFuncAttributeMaxDynamicSharedMemorySize, TG3_SMEM);
    cudaFuncSetAttribute(lstm_kernel,     cudaFuncAttributeMaxDynamicSharedMemorySize, LS_SMEM);
    cudaFuncSetAttribute(sinkhorn_kernel, cudaFuncAttributeMaxDynamicSharedMemorySize, SK_SMEM);

    // 1) prep: Whh transpose, bias sum, weight fp16 splits
    prep_kernel<<<128, 256>>>(w_hh, b_ih, b_hh, w_ih, w_fc1, w_fc2);
    // 2) embed -> xs fp16 hi, rows [t*BATCH+b]
    embed_kernel<<<dim3(1, MROWS/128), 256, 2*128*(FIN/4)*16>>>(x, w_emb, b_emb, xsh);
    // 3) gemm3: A = xs @ Wih^T, 2-product, fp16 output (halves A traffic)
    tgemm2_kernel<<<dim3(NL*GATE/128, MROWS/128), 256, TG2_SMEM>>>(
        xsh, wihh, wihl, zero, Ab, nullptr, nullptr, NL*GATE, NL*GATE, NL*GATE, 0);
    // 4) LSTM recurrence -> hs fp16 hi (rows [b*SEQ+t])
    lstm_kernel<<<BATCH/4, 256, LS_SMEM>>>(Ab, hsh);
    // 5) fc1 (leaky) -> f1 fp16 split (lo kept: fc2 reads it), 2-product
    tgemm2_kernel<<<dim3(1, MROWS/128), 256, TG2_SMEM>>>(
        hsh, wf1h, wf1l, b_fc1, nullptr, f1h, f1l, EMB, EMB, EMB, 1);
    // 6) fc2 -> M fp32, 3-product (output path)
    tgemm3_kernel<<<dim3(2, MROWS/128), 256, TG3_SMEM>>>(
        f1h, f1l, wf2h, wf2l, b_fc2, Mb, SEQ, SEQ, SEQ);
    // 7) sinkhorn (fused row+col passes, FMA-pipe exp)
    sinkhorn_kernel<<<BATCH, 512, SK_SMEM>>>(Mb, out);
}

// round 13
// speedup vs baseline: 1.0931x; 1.0931x over previous
#include <cuda_runtime.h>
#include <cuda_fp16.h>
#include <mma.h>
#include <math.h>
#include <stdint.h>

#define BATCH 512
#define SEQ   200
#define FIN   32
#define EMB   128
#define HID   128
#define GATE  512            // 4*HID
#define NL    2
#define MROWS (BATCH*SEQ)    // 102400
#define KDIM  128

// ---------------- scratch (__device__ globals) ----------------
__device__ float  g_A [(size_t)MROWS*NL*GATE];          // LSTM input projections (fp32), [t][b] rows
__device__ float  g_Mb[(size_t)MROWS*SEQ];              // fc2 out [b][n][n']
__device__ float4 g_Wt4[NL*(HID/4)*GATE];               // Whh transposed k-major
__device__ float  g_blstm[NL*GATE];                     // b_ih + b_hh
__device__ float  g_zero[NL*GATE];                      // zero bias for gemm3

// fp16 operands for tensor GEMMs (lo-parts only where actually consumed)
__device__ __half g_xsh[(size_t)MROWS*EMB];                             // [t][b] rows
__device__ __half g_wihh[NL*GATE*EMB],      g_wihl[NL*GATE*EMB];
__device__ __half g_wf1h[EMB*HID],          g_wf1l[EMB*HID];
__device__ __half g_wf2h[SEQ*EMB],          g_wf2l[SEQ*EMB];
__device__ __half g_hsh[(size_t)MROWS*HID];                             // [b][t] rows
__device__ __half g_f1h[(size_t)MROWS*EMB], g_f1l[(size_t)MROWS*EMB];

__device__ __forceinline__ void split2h(float v, __half& h, __half& l) {
    h = __float2half_rn(v);
    l = __float2half_rn(v - __half2float(h));
}

// packed fp32x2 FMA (embed + lstm scalar paths)
union f4u { float4 f4; unsigned long long u[2]; };
__device__ __forceinline__ void ffma2(unsigned long long& d,
                                      unsigned long long a,
                                      unsigned long long b) {
    asm("fma.rn.f32x2 %0, %1, %2, %0;" : "+l"(d) : "l"(a), "l"(b));
}
__device__ __forceinline__ float hadd2(unsigned long long v) {
    union { unsigned long long u; float2 f; } c; c.u = v;
    return c.f.x + c.f.y;
}

// fast activations (MUFU-based; lstm only — low volume there)
__device__ __forceinline__ float fsig(float x)  { return __fdividef(1.f, 1.f + __expf(-x)); }
__device__ __forceinline__ float ftanh(float x) { return __fdividef(2.f, 1.f + __expf(-2.f*x)) - 1.f; }

// polynomial exp on FMA pipe (avoids MUFU bottleneck; rel err ~1e-6)
__device__ __forceinline__ float fexp(float x) {
    float t = x * 1.4426950408889634f;     // x * log2(e)
    float r = rintf(t);
    float y = (t - r) * 0.6931471805599453f;
    float p = 0.008333333f;
    p = fmaf(p, y, 0.041666667f);
    p = fmaf(p, y, 0.16666667f);
    p = fmaf(p, y, 0.5f);
    p = fmaf(p, y, 1.0f);
    p = fmaf(p, y, 1.0f);
    float s = __int_as_float(((int)r + 127) << 23);
    return p * s;
}

// ---------------- prep: Whh transpose, bias sums, weight fp16 splits ----------------
__global__ void prep_kernel(const float* __restrict__ w_hh,
                            const float* __restrict__ b_ih,
                            const float* __restrict__ b_hh,
                            const float* __restrict__ w_ih,
                            const float* __restrict__ w_fc1,
                            const float* __restrict__ w_fc2) {
    int idx = blockIdx.x*blockDim.x + threadIdx.x;
    int stride = gridDim.x*blockDim.x;
    const int tot = NL*(HID/4)*GATE;
    for (int q = idx; q < tot; q += stride) {
        int j  = q % GATE;
        int k4 = (q / GATE) % (HID/4);
        int l  = q / (GATE*(HID/4));
        const float* wr = w_hh + ((size_t)(l*GATE + j))*HID + k4*4;
        g_Wt4[q] = make_float4(wr[0], wr[1], wr[2], wr[3]);
    }
    for (int q = idx; q < NL*GATE; q += stride) {
        g_blstm[q] = b_ih[q] + b_hh[q];
        g_zero[q]  = 0.f;
    }
    for (int q = idx; q < NL*GATE*EMB; q += stride) split2h(w_ih[q],  g_wihh[q], g_wihl[q]);
    for (int q = idx; q < EMB*HID;     q += stride) split2h(w_fc1[q], g_wf1h[q], g_wf1l[q]);
    for (int q = idx; q < SEQ*EMB;     q += stride) split2h(w_fc2[q], g_wf2h[q], g_wf2l[q]);
}

// ---------------- embed: e = leaky(x @ w_emb^T + b) -> fp16 hi, rows [t*BATCH+b] -------
__global__ __launch_bounds__(256) void embed_kernel(
    const float* __restrict__ A, const float* __restrict__ B,
    const float* __restrict__ bias,
    __half* __restrict__ outh)
{
    const int K = FIN, K4 = FIN/4, N = EMB;
    extern __shared__ float4 sm4[];
    float4* As4 = sm4;
    float4* Bs4 = sm4 + 128*K4;

    const int m0 = blockIdx.y * 128;
    const int tid = threadIdx.x;

    for (int q = tid; q < 128*K4; q += 256) {
        int row = q / K4, k4 = q % K4;
        As4[row*K4 + (k4 ^ ((row>>3)&7))] = *(const float4*)(A + ((size_t)(m0+row))*K + (k4<<2));
    }
    for (int q = tid; q < 128*K4; q += 256) {
        int row = q / K4, k4 = q % K4;
        Bs4[row*K4 + (k4 ^ ((row>>3)&7))] = *(const float4*)(B + ((size_t)row)*K + (k4<<2));
    }
    __syncthreads();

    const int tx = tid & 15, ty = tid >> 4;
    const int swa = ty & 7, swb = tx & 7;

    unsigned long long acc[8][8];
    #pragma unroll
    for (int i = 0; i < 8; i++)
        #pragma unroll
        for (int j = 0; j < 8; j++) acc[i][j] = 0ULL;

    for (int k4 = 0; k4 < K4; k4++) {
        int ka = (k4 ^ swa) & (K4-1), kb = (k4 ^ swb) & (K4-1);
        f4u av[8];
        #pragma unroll
        for (int ii = 0; ii < 8; ii++) av[ii].f4 = As4[(ty*8+ii)*K4 + ka];
        #pragma unroll
        for (int jj = 0; jj < 8; jj++) {
            f4u bv; bv.f4 = Bs4[(tx*8+jj)*K4 + kb];
            #pragma unroll
            for (int ii = 0; ii < 8; ii++) {
                ffma2(acc[ii][jj], av[ii].u[0], bv.u[0]);
                ffma2(acc[ii][jj], av[ii].u[1], bv.u[1]);
            }
        }
    }

    #pragma unroll
    for (int ii = 0; ii < 8; ii++) {
        int m = m0 + ty*8 + ii;
        int b = m / SEQ, t = m - b*SEQ;
        size_t orow = (size_t)t*BATCH + b;     // [t][b] row remap for gemm3/lstm locality
        union { unsigned short s[8]; uint4 v; } ph;
        #pragma unroll
        for (int jj = 0; jj < 8; jj++) {
            int n = tx*8 + jj;
            float v = hadd2(acc[ii][jj]) + bias[n];
            v = (v >= 0.f) ? v : 0.01f*v;
            ph.s[jj] = __half_as_ushort(__float2half_rn(v));
        }
        *(uint4*)(outh + orow*N + tx*8) = ph.v;
    }
}

// ---------------- tgemm2: C = act(A @ (Bh+Bl)^T + bias), 2-product fp16 ---------------
// 3 smem tiles (102KB) -> 2 CTAs/SM. C: fp32 (gemm3 path) or fp16 hi/lo split (fc1).
__global__ __launch_bounds__(256, 2) void tgemm2_kernel(
    const __half* __restrict__ Ah,
    const __half* __restrict__ Bh, const __half* __restrict__ Bl,
    const float* __restrict__ bias, float* __restrict__ C,
    __half* __restrict__ Ch, __half* __restrict__ Cl,
    int Ntot, int ldC, int Brows, int act)
{
    using namespace nvcuda;
    const int LDT = 136;
    extern __shared__ __align__(32) char smem[];
    __half* sAh = (__half*)smem;
    __half* sBh = sAh + 128*LDT;
    __half* sBl = sBh + 128*LDT;

    const int tid = threadIdx.x;
    const int w = tid >> 5, lane = tid & 31;
    const int wm = w >> 1, wn = w & 1;          // 4x2 warp grid
    const int m0 = blockIdx.y * 128;
    const int n0 = blockIdx.x * 128;

    for (int q = tid; q < 128*16; q += 256) {
        int row = q >> 4, c = q & 15;
        uint4 va  = *(const uint4*)(Ah + (size_t)(m0+row)*KDIM + c*8);
        uint4 vb  = make_uint4(0u,0u,0u,0u), vbl = make_uint4(0u,0u,0u,0u);
        if (n0 + row < Brows) {
            vb  = *(const uint4*)(Bh + (size_t)(n0+row)*KDIM + c*8);
            vbl = *(const uint4*)(Bl + (size_t)(n0+row)*KDIM + c*8);
        }
        *(uint4*)(sAh + row*LDT + c*8) = va;
        *(uint4*)(sBh + row*LDT + c*8) = vb;
        *(uint4*)(sBl + row*LDT + c*8) = vbl;
    }
    __syncthreads();

    wmma::fragment<wmma::accumulator, 16, 16, 16, float> acc[2][4];
    #pragma unroll
    for (int ti = 0; ti < 2; ti++)
        #pragma unroll
        for (int tj = 0; tj < 4; tj++) wmma::fill_fragment(acc[ti][tj], 0.0f);

    #pragma unroll 2
    for (int ks = 0; ks < 8; ks++) {
        wmma::fragment<wmma::matrix_a, 16, 16, 16, __half, wmma::row_major> ah[2];
        #pragma unroll
        for (int ti = 0; ti < 2; ti++)
            wmma::load_matrix_sync(ah[ti], sAh + (wm*32 + ti*16)*LDT + ks*16, LDT);
        #pragma unroll
        for (int tj = 0; tj < 4; tj++) {
            int nrow = wn*64 + tj*16;
            wmma::fragment<wmma::matrix_b, 16, 16, 16, __half, wmma::col_major> bh, bl;
            wmma::load_matrix_sync(bh, sBh + nrow*LDT + ks*16, LDT);
            wmma::load_matrix_sync(bl, sBl + nrow*LDT + ks*16, LDT);
            #pragma unroll
            for (int ti = 0; ti < 2; ti++) {
                wmma::mma_sync(acc[ti][tj], ah[ti], bh, acc[ti][tj]);
                wmma::mma_sync(acc[ti][tj], ah[ti], bl, acc[ti][tj]);
            }
        }
    }
    __syncthreads();   // tiles dead; reuse smem front as per-warp stage

    float* stg = (float*)smem + w*16*20;
    const int r = lane >> 1, seg = lane & 1;
    #pragma unroll 1
    for (int ti = 0; ti < 2; ti++)
    #pragma unroll 1
    for (int tj = 0; tj < 4; tj++) {
        wmma::store_matrix_sync(stg, acc[ti][tj], 20, wmma::mem_row_major);
        __syncwarp();
        size_t orow = (size_t)(m0 + wm*32 + ti*16 + r);
        int nbase = n0 + wn*64 + tj*16 + seg*8;
        float v[8];
        #pragma unroll
        for (int i = 0; i < 8; i++) {
            int n = nbase + i;
            float t = stg[r*20 + seg*8 + i] + ((n < Ntot) ? bias[n] : 0.f);
            if (act) t = (t >= 0.f) ? t : 0.01f*t;
            v[i] = t;
        }
        if (C) {
            if (nbase + 8 <= Ntot) {
                *(float4*)(C + orow*ldC + nbase)     = make_float4(v[0],v[1],v[2],v[3]);
                *(float4*)(C + orow*ldC + nbase + 4) = make_float4(v[4],v[5],v[6],v[7]);
            } else {
                for (int i = 0; i < 8; i++)
                    if (nbase + i < Ntot) C[orow*ldC + nbase + i] = v[i];
            }
        } else {
            union { unsigned short s[8]; uint4 q; } ph, pl;
            #pragma unroll
            for (int i = 0; i < 8; i++) {
                __half h, l; split2h(v[i], h, l);
                ph.s[i] = __half_as_ushort(h);
                pl.s[i] = __half_as_ushort(l);
            }
            *(uint4*)(Ch + orow*ldC + nbase) = ph.q;
            *(uint4*)(Cl + orow*ldC + nbase) = pl.q;
        }
        __syncwarp();
    }
}

// ---------------- tgemm3: C = (Ah+Al) @ (Bh+Bl)^T + bias (3-product, output path) -----
__global__ __launch_bounds__(256) void tgemm3_kernel(
    const __half* __restrict__ Ah, const __half* __restrict__ Al,
    const __half* __restrict__ Bh, const __half* __restrict__ Bl,
    const float* __restrict__ bias, float* __restrict__ C,
    int Ntot, int ldC, int Brows)
{
    using namespace nvcuda;
    const int LDT = 136;
    extern __shared__ __align__(32) char smem[];
    __half* sAh = (__half*)smem;
    __half* sAl = sAh + 128*LDT;
    __half* sBh = sAl + 128*LDT;
    __half* sBl = sBh + 128*LDT;

    const int tid = threadIdx.x;
    const int w = tid >> 5, lane = tid & 31;
    const int wm = w >> 1, wn = w & 1;
    const int m0 = blockIdx.y * 128;
    const int n0 = blockIdx.x * 128;

    for (int q = tid; q < 128*16; q += 256) {
        int row = q >> 4, c = q & 15;
        uint4 va  = *(const uint4*)(Ah + (size_t)(m0+row)*KDIM + c*8);
        uint4 val = *(const uint4*)(Al + (size_t)(m0+row)*KDIM + c*8);
        uint4 vb  = make_uint4(0u,0u,0u,0u), vbl = make_uint4(0u,0u,0u,0u);
        if (n0 + row < Brows) {
            vb  = *(const uint4*)(Bh + (size_t)(n0+row)*KDIM + c*8);
            vbl = *(const uint4*)(Bl + (size_t)(n0+row)*KDIM + c*8);
        }
        *(uint4*)(sAh + row*LDT + c*8) = va;
        *(uint4*)(sAl + row*LDT + c*8) = val;
        *(uint4*)(sBh + row*LDT + c*8) = vb;
        *(uint4*)(sBl + row*LDT + c*8) = vbl;
    }
    __syncthreads();

    wmma::fragment<wmma::accumulator, 16, 16, 16, float> acc[2][4];
    #pragma unroll
    for (int ti = 0; ti < 2; ti++)
        #pragma unroll
        for (int tj = 0; tj < 4; tj++) wmma::fill_fragment(acc[ti][tj], 0.0f);

    #pragma unroll 2
    for (int ks = 0; ks < 8; ks++) {
        wmma::fragment<wmma::matrix_a, 16, 16, 16, __half, wmma::row_major> ah[2], al[2];
        #pragma unroll
        for (int ti = 0; ti < 2; ti++) {
            int mrow = wm*32 + ti*16;
            wmma::load_matrix_sync(ah[ti], sAh + mrow*LDT + ks*16, LDT);
            wmma::load_matrix_sync(al[ti], sAl + mrow*LDT + ks*16, LDT);
        }
        wmma::fragment<wmma::matrix_b, 16, 16, 16, __half, wmma::col_major> bh[4], bl[4];
        #pragma unroll
        for (int tj = 0; tj < 4; tj++) {
            int nrow = wn*64 + tj*16;
            wmma::load_matrix_sync(bh[tj], sBh + nrow*LDT + ks*16, LDT);
            wmma::load_matrix_sync(bl[tj], sBl + nrow*LDT + ks*16, LDT);
        }
        #pragma unroll
        for (int ti = 0; ti < 2; ti++)
            #pragma unroll
            for (int tj = 0; tj < 4; tj++) {
                wmma::mma_sync(acc[ti][tj], ah[ti], bh[tj], acc[ti][tj]);
                wmma::mma_sync(acc[ti][tj], ah[ti], bl[tj], acc[ti][tj]);
                wmma::mma_sync(acc[ti][tj], al[ti], bh[tj], acc[ti][tj]);
            }
    }
    __syncthreads();

    float* stg = (float*)smem + w*16*20;
    const int r = lane >> 1, seg = lane & 1;
    #pragma unroll 1
    for (int ti = 0; ti < 2; ti++)
    #pragma unroll 1
    for (int tj = 0; tj < 4; tj++) {
        wmma::store_matrix_sync(stg, acc[ti][tj], 20, wmma::mem_row_major);
        __syncwarp();
        size_t orow = (size_t)(m0 + wm*32 + ti*16 + r);
        int nbase = n0 + wn*64 + tj*16 + seg*8;
        float v[8];
        #pragma unroll
        for (int i = 0; i < 8; i++) {
            int n = nbase + i;
            v[i] = stg[r*20 + seg*8 + i] + ((n < Ntot) ? bias[n] : 0.f);
        }
        if (nbase + 8 <= Ntot) {
            *(float4*)(C + orow*ldC + nbase)     = make_float4(v[0],v[1],v[2],v[3]);
            *(float4*)(C + orow*ldC + nbase + 4) = make_float4(v[4],v[5],v[6],v[7]);
        } else {
            for (int i = 0; i < 8; i++)
                if (nbase + i < Ntot) C[orow*ldC + nbase + i] = v[i];
        }
        __syncwarp();
    }
}

// ---------------- LSTM recurrence: 256 threads, 2 gates x 4 batches per thread --------
// A rows are [t*BATCH+b] fp32: per step the grid reads one contiguous 2MB slab.
#define KC 16
#define KR 16
__global__ __launch_bounds__(256) void lstm_kernel(const float* __restrict__ A,
                                                   __half* __restrict__ hsh)
{
    __shared__ float h_s[4][HID];
    __shared__ float c_s[4][HID];
    __shared__ float g_s[4][GATE];
    extern __shared__ float4 Wc[];   // KC*GATE float4 = 128 KB

    const int tid = threadIdx.x;
    const int j0 = tid, j1 = tid + 256;
    const int bb = blockIdx.x * 4;
    const int ub0 = tid >> 7,      uh = tid & 127;
    const int ub1 = 2 + (tid >> 7);

    h_s[ub0][uh] = 0.f; h_s[ub1][uh] = 0.f;
    c_s[ub0][uh] = 0.f; c_s[ub1][uh] = 0.f;

    for (int l = 0; l < NL; l++) {
        const float4* W = g_Wt4 + l*(HID/4)*GATE;
        const float bias0 = g_blstm[l*GATE + j0];
        const float bias1 = g_blstm[l*GATE + j1];
        __syncthreads();
        for (int q = tid; q < KC*GATE; q += 256) Wc[q] = W[q];
        f4u w0[KR], w1[KR];
        #pragma unroll
        for (int r = 0; r < KR; r++) {
            w0[r].f4 = W[(KC+r)*GATE + j0];
            w1[r].f4 = W[(KC+r)*GATE + j1];
        }
        __syncthreads();

        float a0[4], a1[4];
        {
            const float* Ar = A + (size_t)bb*(NL*GATE) + l*GATE;
            #pragma unroll
            for (int b = 0; b < 4; b++) {
                a0[b] = Ar[(size_t)b*(NL*GATE) + j0];
                a1[b] = Ar[(size_t)b*(NL*GATE) + j1];
            }
        }

        for (int t = 0; t < SEQ; t++) {
            float na0[4], na1[4];
            if (t + 1 < SEQ) {
                const float* Arn = A + ((size_t)((t+1)*BATCH + bb))*(NL*GATE) + l*GATE;
                #pragma unroll
                for (int b = 0; b < 4; b++) {
                    na0[b] = Arn[(size_t)b*(NL*GATE) + j0];
                    na1[b] = Arn[(size_t)b*(NL*GATE) + j1];
                }
            } else {
                #pragma unroll
                for (int b = 0; b < 4; b++) { na0[b] = 0.f; na1[b] = 0.f; }
            }

            unsigned long long s0[4] = {0,0,0,0}, s1[4] = {0,0,0,0};
            #pragma unroll
            for (int k4 = 0; k4 < KC; k4++) {
                f4u wv0; wv0.f4 = Wc[k4*GATE + j0];
                f4u wv1; wv1.f4 = Wc[k4*GATE + j1];
                #pragma unroll
                for (int b = 0; b < 4; b++) {
                    f4u hb; hb.f4 = *(const float4*)&h_s[b][k4<<2];
                    ffma2(s0[b], wv0.u[0], hb.u[0]); ffma2(s0[b], wv0.u[1], hb.u[1]);
                    ffma2(s1[b], wv1.u[0], hb.u[0]); ffma2(s1[b], wv1.u[1], hb.u[1]);
                }
            }
            #pragma unroll
            for (int r = 0; r < KR; r++) {
                int k4 = KC + r;
                #pragma unroll
                for (int b = 0; b < 4; b++) {
                    f4u hb; hb.f4 = *(const float4*)&h_s[b][k4<<2];
                    ffma2(s0[b], w0[r].u[0], hb.u[0]); ffma2(s0[b], w0[r].u[1], hb.u[1]);
                    ffma2(s1[b], w1[r].u[0], hb.u[0]); ffma2(s1[b], w1[r].u[1], hb.u[1]);
                }
            }
            #pragma unroll
            for (int b = 0; b < 4; b++) {
                g_s[b][j0] = hadd2(s0[b]) + a0[b] + bias0;
                g_s[b][j1] = hadd2(s1[b]) + a1[b] + bias1;
            }
            __syncthreads();

            #pragma unroll
            for (int p = 0; p < 2; p++) {
                int b = p ? ub1 : ub0;
                float ig = g_s[b][uh];
                float fg = g_s[b][HID   + uh];
                float gg = g_s[b][2*HID + uh];
                float og = g_s[b][3*HID + uh];
                float cc = fsig(fg)*c_s[b][uh] + fsig(ig)*ftanh(gg);
                float hh = fsig(og)*ftanh(cc);
                c_s[b][uh] = cc;
                h_s[b][uh] = hh;
                if (l == NL-1)
                    hsh[((size_t)(bb+b)*SEQ + t)*HID + uh] = __float2half_rn(hh);
            }
            __syncthreads();
            #pragma unroll
            for (int b = 0; b < 4; b++) { a0[b] = na0[b]; a1[b] = na1[b]; }
        }
    }
}

// ---------------- sinkhorn: fused row+col pass, poly exp, register col sums -----------
__global__ __launch_bounds__(512) void sinkhorn_kernel(const float* __restrict__ Min,
                                                       float* __restrict__ out)
{
    extern __shared__ float Ms[];               // SEQ*SEQ
    float* colpart = Ms + SEQ*SEQ;              // 16*SEQ
    float* colinv  = colpart + 16*SEQ;          // SEQ
    const int b = blockIdx.x, tid = threadIdx.x;
    const int lane = tid & 31, w = tid >> 5;    // 16 warps

    const float4* src = (const float4*)(Min + (size_t)b*SEQ*SEQ);
    for (int q = tid; q < SEQ*SEQ/4; q += 512) {
        float4 v = src[q];
        v.x = fexp(v.x); v.y = fexp(v.y); v.z = fexp(v.z); v.w = fexp(v.w);
        ((float4*)Ms)[q] = v;
    }
    if (tid < SEQ) colinv[tid] = 1.0f;
    __syncthreads();

    for (int it = 0; it < 5; it++) {
        float ci[7], cs[7];
        #pragma unroll
        for (int i = 0; i < 7; i++) {
            int c = lane + 32*i;
            ci[i] = (c < SEQ) ? colinv[c] : 0.f;
            cs[i] = 0.f;
        }
        for (int r = w; r < SEQ; r += 16) {
            float v[7]; float s = 0.f;
            #pragma unroll
            for (int i = 0; i < 7; i++) {
                int c = lane + 32*i;
                float x = (c < SEQ) ? Ms[r*SEQ + c] * ci[i] : 0.f;
                v[i] = x; s += x;
            }
            #pragma unroll
            for (int off = 16; off; off >>= 1) s += __shfl_xor_sync(0xffffffffu, s, off);
            float inv = 1.0f / s;
            #pragma unroll
            for (int i = 0; i < 7; i++) {
                int c = lane + 32*i;
                if (c < SEQ) {
                    float x = v[i] * inv;
                    Ms[r*SEQ + c] = x;
                    cs[i] += x;
                }
            }
        }
        #pragma unroll
        for (int i = 0; i < 7; i++) {
            int c = lane + 32*i;
            if (c < SEQ) colpart[w*SEQ + c] = cs[i];
        }
        __syncthreads();
        if (tid < SEQ) {
            float s = 0.f;
            #pragma unroll
            for (int k = 0; k < 16; k++) s += colpart[k*SEQ + tid];
            colinv[tid] = 1.0f / s;
        }
        __syncthreads();
    }

    float4* dst = (float4*)(out + (size_t)b*SEQ*SEQ);
    for (int q = tid; q < SEQ*SEQ/4; q += 512) {
        float4 v = ((const float4*)Ms)[q];
        int c0 = (q % (SEQ/4)) * 4;
        v.x *= colinv[c0]; v.y *= colinv[c0+1]; v.z *= colinv[c0+2]; v.w *= colinv[c0+3];
        dst[q] = v;
    }
}

// ---------------- launch ----------------
extern "C" void kernel_launch(void* const* d_in, const int* in_sizes, int n_in,
                              void* d_out, int out_size)
{
    const float* x     = (const float*)d_in[0];
    const float* w_emb = (const float*)d_in[1];
    const float* b_emb = (const float*)d_in[2];
    const float* w_ih  = (const float*)d_in[3];
    const float* w_hh  = (const float*)d_in[4];
    const float* b_ih  = (const float*)d_in[5];
    const float* b_hh  = (const float*)d_in[6];
    const float* w_fc1 = (const float*)d_in[7];
    const float* b_fc1 = (const float*)d_in[8];
    const float* w_fc2 = (const float*)d_in[9];
    const float* b_fc2 = (const float*)d_in[10];
    float* out = (float*)d_out;

    float *Ab, *Mb, *zero;
    __half *xsh,*wihh,*wihl,*wf1h,*wf1l,*wf2h,*wf2l,*hsh,*f1h,*f1l;
    cudaGetSymbolAddress((void**)&Ab,   g_A);
    cudaGetSymbolAddress((void**)&Mb,   g_Mb);
    cudaGetSymbolAddress((void**)&zero, g_zero);
    cudaGetSymbolAddress((void**)&xsh,  g_xsh);
    cudaGetSymbolAddress((void**)&wihh, g_wihh); cudaGetSymbolAddress((void**)&wihl, g_wihl);
    cudaGetSymbolAddress((void**)&wf1h, g_wf1h); cudaGetSymbolAddress((void**)&wf1l, g_wf1l);
    cudaGetSymbolAddress((void**)&wf2h, g_wf2h); cudaGetSymbolAddress((void**)&wf2l, g_wf2l);
    cudaGetSymbolAddress((void**)&hsh,  g_hsh);
    cudaGetSymbolAddress((void**)&f1h,  g_f1h);  cudaGetSymbolAddress((void**)&f1l, g_f1l);

    const int TG2_SMEM = 3*128*136*2;         // 104448 (3 tiles -> 2 CTAs/SM)
    const int TG3_SMEM = 4*128*136*2;         // 139264
    const int LS_SMEM  = KC*GATE*16;          // 131072
    const int SK_SMEM  = (SEQ*SEQ + 16*SEQ + SEQ)*4;   // 173600
    cudaFuncSetAttribute(tgemm2_kernel,   cudaFuncAttributeMaxDynamicSharedMemorySize, TG2_SMEM);
    cudaFuncSetAttribute(tgemm3_kernel,   cudaFuncAttributeMaxDynamicSharedMemorySize, TG3_SMEM);
    cudaFuncSetAttribute(lstm_kernel,     cudaFuncAttributeMaxDynamicSharedMemorySize, LS_SMEM);
    cudaFuncSetAttribute(sinkhorn_kernel, cudaFuncAttributeMaxDynamicSharedMemorySize, SK_SMEM);

    // 1) prep: Whh transpose, bias sum, weight fp16 splits
    prep_kernel<<<128, 256>>>(w_hh, b_ih, b_hh, w_ih, w_fc1, w_fc2);
    // 2) embed -> xs fp16 hi, rows [t*BATCH+b]
    embed_kernel<<<dim3(1, MROWS/128), 256, 2*128*(FIN/4)*16>>>(x, w_emb, b_emb, xsh);
    // 3) gemm3: A = xs @ Wih^T, 2-product, fp32 output (lstm's A-stream stays 32-bit)
    tgemm2_kernel<<<dim3(NL*GATE/128, MROWS/128), 256, TG2_SMEM>>>(
        xsh, wihh, wihl, zero, Ab, nullptr, nullptr, NL*GATE, NL*GATE, NL*GATE, 0);
    // 4) LSTM recurrence -> hs fp16 hi (rows [b*SEQ+t])
    lstm_kernel<<<BATCH/4, 256, LS_SMEM>>>(Ab, hsh);
    // 5) fc1 (leaky) -> f1 fp16 split (lo kept: fc2 reads it), 2-product
    tgemm2_kernel<<<dim3(1, MROWS/128), 256, TG2_SMEM>>>(
        hsh, wf1h, wf1l, b_fc1, nullptr, f1h, f1l, EMB, EMB, EMB, 1);
    // 6) fc2 -> M fp32, 3-product (output path)
    tgemm3_kernel<<<dim3(2, MROWS/128), 256, TG3_SMEM>>>(
        f1h, f1l, wf2h, wf2l, b_fc2, Mb, SEQ, SEQ, SEQ);
    // 7) sinkhorn (fused row+col passes, FMA-pipe exp)
    sinkhorn_kernel<<<BATCH, 512, SK_SMEM>>>(Mb, out);
}

// round 15
// speedup vs baseline: 1.1989x; 1.0968x over previous
#include <cuda_runtime.h>
#include <cuda_fp16.h>
#include <mma.h>
#include <math.h>
#include <stdint.h>

#define BATCH 512
#define SEQ   200
#define FIN   32
#define EMB   128
#define HID   128
#define GATE  512            // 4*HID
#define NL    2
#define MROWS (BATCH*SEQ)    // 102400
#define KDIM  128

// ---------------- scratch (__device__ globals) ----------------
__device__ float  g_A [(size_t)MROWS*NL*GATE];          // LSTM input projections (fp32), [t][b] rows
__device__ float  g_Mb[(size_t)MROWS*SEQ];              // fc2 out [b][n][n']
__device__ float4 g_Wt4[NL*(HID/4)*GATE];               // Whh transposed k-major
__device__ float  g_blstm[NL*GATE];                     // b_ih + b_hh
__device__ float  g_zero[NL*GATE];                      // zero bias for gemm3

// fp16 operands for tensor GEMMs
__device__ __half g_xsh[(size_t)MROWS*EMB];                             // [t][b] rows
__device__ __half g_wih [NL*GATE*EMB];                                  // fp16 (1-product)
__device__ __half g_wf1 [EMB*HID];                                      // fp16 (1-product)
__device__ __half g_wf2h[SEQ*EMB],          g_wf2l[SEQ*EMB];            // split (3-product)
__device__ __half g_hsh[(size_t)MROWS*HID];                             // [b][t] rows
__device__ __half g_f1h[(size_t)MROWS*EMB], g_f1l[(size_t)MROWS*EMB];

__device__ __forceinline__ void split2h(float v, __half& h, __half& l) {
    h = __float2half_rn(v);
    l = __float2half_rn(v - __half2float(h));
}

// packed fp32x2 FMA (embed + lstm scalar paths)
union f4u { float4 f4; unsigned long long u[2]; };
__device__ __forceinline__ void ffma2(unsigned long long& d,
                                      unsigned long long a,
                                      unsigned long long b) {
    asm("fma.rn.f32x2 %0, %1, %2, %0;" : "+l"(d) : "l"(a), "l"(b));
}
__device__ __forceinline__ float hadd2(unsigned long long v) {
    union { unsigned long long u; float2 f; } c; c.u = v;
    return c.f.x + c.f.y;
}

// fast activations (MUFU-based)
__device__ __forceinline__ float fsig(float x)  { return __fdividef(1.f, 1.f + __expf(-x)); }
__device__ __forceinline__ float ftanh(float x) { return __fdividef(2.f, 1.f + __expf(-2.f*x)) - 1.f; }

// ---------------- prep: Whh transpose, bias sums, weight fp16 conversions -------------
__global__ void prep_kernel(const float* __restrict__ w_hh,
                            const float* __restrict__ b_ih,
                            const float* __restrict__ b_hh,
                            const float* __restrict__ w_ih,
                            const float* __restrict__ w_fc1,
                            const float* __restrict__ w_fc2) {
    int idx = blockIdx.x*blockDim.x + threadIdx.x;
    int stride = gridDim.x*blockDim.x;
    const int tot = NL*(HID/4)*GATE;
    for (int q = idx; q < tot; q += stride) {
        int j  = q % GATE;
        int k4 = (q / GATE) % (HID/4);
        int l  = q / (GATE*(HID/4));
        const float* wr = w_hh + ((size_t)(l*GATE + j))*HID + k4*4;
        g_Wt4[q] = make_float4(wr[0], wr[1], wr[2], wr[3]);
    }
    for (int q = idx; q < NL*GATE; q += stride) {
        g_blstm[q] = b_ih[q] + b_hh[q];
        g_zero[q]  = 0.f;
    }
    for (int q = idx; q < NL*GATE*EMB; q += stride) g_wih[q] = __float2half_rn(w_ih[q]);
    for (int q = idx; q < EMB*HID;     q += stride) g_wf1[q] = __float2half_rn(w_fc1[q]);
    for (int q = idx; q < SEQ*EMB;     q += stride) split2h(w_fc2[q], g_wf2h[q], g_wf2l[q]);
}

// ---------------- embed: e = leaky(x @ w_emb^T + b) -> fp16 hi, rows [t*BATCH+b] -------
__global__ __launch_bounds__(256) void embed_kernel(
    const float* __restrict__ A, const float* __restrict__ B,
    const float* __restrict__ bias,
    __half* __restrict__ outh)
{
    const int K = FIN, K4 = FIN/4, N = EMB;
    extern __shared__ float4 sm4[];
    float4* As4 = sm4;
    float4* Bs4 = sm4 + 128*K4;

    const int m0 = blockIdx.y * 128;
    const int tid = threadIdx.x;

    for (int q = tid; q < 128*K4; q += 256) {
        int row = q / K4, k4 = q % K4;
        As4[row*K4 + (k4 ^ ((row>>3)&7))] = *(const float4*)(A + ((size_t)(m0+row))*K + (k4<<2));
    }
    for (int q = tid; q < 128*K4; q += 256) {
        int row = q / K4, k4 = q % K4;
        Bs4[row*K4 + (k4 ^ ((row>>3)&7))] = *(const float4*)(B + ((size_t)row)*K + (k4<<2));
    }
    __syncthreads();

    const int tx = tid & 15, ty = tid >> 4;
    const int swa = ty & 7, swb = tx & 7;

    unsigned long long acc[8][8];
    #pragma unroll
    for (int i = 0; i < 8; i++)
        #pragma unroll
        for (int j = 0; j < 8; j++) acc[i][j] = 0ULL;

    for (int k4 = 0; k4 < K4; k4++) {
        int ka = (k4 ^ swa) & (K4-1), kb = (k4 ^ swb) & (K4-1);
        f4u av[8];
        #pragma unroll
        for (int ii = 0; ii < 8; ii++) av[ii].f4 = As4[(ty*8+ii)*K4 + ka];
        #pragma unroll
        for (int jj = 0; jj < 8; jj++) {
            f4u bv; bv.f4 = Bs4[(tx*8+jj)*K4 + kb];
            #pragma unroll
            for (int ii = 0; ii < 8; ii++) {
                ffma2(acc[ii][jj], av[ii].u[0], bv.u[0]);
                ffma2(acc[ii][jj], av[ii].u[1], bv.u[1]);
            }
        }
    }

    #pragma unroll
    for (int ii = 0; ii < 8; ii++) {
        int m = m0 + ty*8 + ii;
        int b = m / SEQ, t = m - b*SEQ;
        size_t orow = (size_t)t*BATCH + b;     // [t][b] row remap for gemm3/lstm locality
        union { unsigned short s[8]; uint4 v; } ph;
        #pragma unroll
        for (int jj = 0; jj < 8; jj++) {
            int n = tx*8 + jj;
            float v = hadd2(acc[ii][jj]) + bias[n];
            v = (v >= 0.f) ? v : 0.01f*v;
            ph.s[jj] = __half_as_ushort(__float2half_rn(v));
        }
        *(uint4*)(outh + orow*N + tx*8) = ph.v;
    }
}

// ---------------- tgemm1: C = act(A @ B^T + bias), plain fp16, fp32 acc ---------------
// 2 smem tiles (68KB) -> 2 CTAs/SM. C: fp32 (gemm3 path) or fp16 hi/lo split (fc1).
__global__ __launch_bounds__(256, 2) void tgemm1_kernel(
    const __half* __restrict__ Ah, const __half* __restrict__ Bh,
    const float* __restrict__ bias, float* __restrict__ C,
    __half* __restrict__ Ch, __half* __restrict__ Cl,
    int Ntot, int ldC, int Brows, int act)
{
    using namespace nvcuda;
    const int LDT = 136;
    extern __shared__ __align__(32) char smem[];
    __half* sAh = (__half*)smem;
    __half* sBh = sAh + 128*LDT;

    const int tid = threadIdx.x;
    const int w = tid >> 5, lane = tid & 31;
    const int wm = w >> 1, wn = w & 1;          // 4x2 warp grid
    const int m0 = blockIdx.y * 128;
    const int n0 = blockIdx.x * 128;

    for (int q = tid; q < 128*16; q += 256) {
        int row = q >> 4, c = q & 15;
        uint4 va  = *(const uint4*)(Ah + (size_t)(m0+row)*KDIM + c*8);
        uint4 vb  = make_uint4(0u,0u,0u,0u);
        if (n0 + row < Brows)
            vb = *(const uint4*)(Bh + (size_t)(n0+row)*KDIM + c*8);
        *(uint4*)(sAh + row*LDT + c*8) = va;
        *(uint4*)(sBh + row*LDT + c*8) = vb;
    }
    __syncthreads();

    wmma::fragment<wmma::accumulator, 16, 16, 16, float> acc[2][4];
    #pragma unroll
    for (int ti = 0; ti < 2; ti++)
        #pragma unroll
        for (int tj = 0; tj < 4; tj++) wmma::fill_fragment(acc[ti][tj], 0.0f);

    #pragma unroll 2
    for (int ks = 0; ks < 8; ks++) {
        wmma::fragment<wmma::matrix_a, 16, 16, 16, __half, wmma::row_major> ah[2];
        #pragma unroll
        for (int ti = 0; ti < 2; ti++)
            wmma::load_matrix_sync(ah[ti], sAh + (wm*32 + ti*16)*LDT + ks*16, LDT);
        #pragma unroll
        for (int tj = 0; tj < 4; tj++) {
            int nrow = wn*64 + tj*16;
            wmma::fragment<wmma::matrix_b, 16, 16, 16, __half, wmma::col_major> bh;
            wmma::load_matrix_sync(bh, sBh + nrow*LDT + ks*16, LDT);
            #pragma unroll
            for (int ti = 0; ti < 2; ti++)
                wmma::mma_sync(acc[ti][tj], ah[ti], bh, acc[ti][tj]);
        }
    }
    __syncthreads();   // tiles dead; reuse smem front as per-warp stage

    float* stg = (float*)smem + w*16*20;
    const int r = lane >> 1, seg = lane & 1;
    #pragma unroll 1
    for (int ti = 0; ti < 2; ti++)
    #pragma unroll 1
    for (int tj = 0; tj < 4; tj++) {
        wmma::store_matrix_sync(stg, acc[ti][tj], 20, wmma::mem_row_major);
        __syncwarp();
        size_t orow = (size_t)(m0 + wm*32 + ti*16 + r);
        int nbase = n0 + wn*64 + tj*16 + seg*8;
        float v[8];
        #pragma unroll
        for (int i = 0; i < 8; i++) {
            int n = nbase + i;
            float t = stg[r*20 + seg*8 + i] + ((n < Ntot) ? bias[n] : 0.f);
            if (act) t = (t >= 0.f) ? t : 0.01f*t;
            v[i] = t;
        }
        if (C) {
            if (nbase + 8 <= Ntot) {
                *(float4*)(C + orow*ldC + nbase)     = make_float4(v[0],v[1],v[2],v[3]);
                *(float4*)(C + orow*ldC + nbase + 4) = make_float4(v[4],v[5],v[6],v[7]);
            } else {
                for (int i = 0; i < 8; i++)
                    if (nbase + i < Ntot) C[orow*ldC + nbase + i] = v[i];
            }
        } else {
            union { unsigned short s[8]; uint4 q; } ph, pl;
            #pragma unroll
            for (int i = 0; i < 8; i++) {
                __half h, l; split2h(v[i], h, l);
                ph.s[i] = __half_as_ushort(h);
                pl.s[i] = __half_as_ushort(l);
            }
            *(uint4*)(Ch + orow*ldC + nbase) = ph.q;
            *(uint4*)(Cl + orow*ldC + nbase) = pl.q;
        }
        __syncwarp();
    }
}

// ---------------- tgemm3: C = (Ah+Al) @ (Bh+Bl)^T + bias (3-product, output path) -----
__global__ __launch_bounds__(256) void tgemm3_kernel(
    const __half* __restrict__ Ah, const __half* __restrict__ Al,
    const __half* __restrict__ Bh, const __half* __restrict__ Bl,
    const float* __restrict__ bias, float* __restrict__ C,
    int Ntot, int ldC, int Brows)
{
    using namespace nvcuda;
    const int LDT = 136;
    extern __shared__ __align__(32) char smem[];
    __half* sAh = (__half*)smem;
    __half* sAl = sAh + 128*LDT;
    __half* sBh = sAl + 128*LDT;
    __half* sBl = sBh + 128*LDT;

    const int tid = threadIdx.x;
    const int w = tid >> 5, lane = tid & 31;
    const int wm = w >> 1, wn = w & 1;
    const int m0 = blockIdx.y * 128;
    const int n0 = blockIdx.x * 128;

    for (int q = tid; q < 128*16; q += 256) {
        int row = q >> 4, c = q & 15;
        uint4 va  = *(const uint4*)(Ah + (size_t)(m0+row)*KDIM + c*8);
        uint4 val = *(const uint4*)(Al + (size_t)(m0+row)*KDIM + c*8);
        uint4 vb  = make_uint4(0u,0u,0u,0u), vbl = make_uint4(0u,0u,0u,0u);
        if (n0 + row < Brows) {
            vb  = *(const uint4*)(Bh + (size_t)(n0+row)*KDIM + c*8);
            vbl = *(const uint4*)(Bl + (size_t)(n0+row)*KDIM + c*8);
        }
        *(uint4*)(sAh + row*LDT + c*8) = va;
        *(uint4*)(sAl + row*LDT + c*8) = val;
        *(uint4*)(sBh + row*LDT + c*8) = vb;
        *(uint4*)(sBl + row*LDT + c*8) = vbl;
    }
    __syncthreads();

    wmma::fragment<wmma::accumulator, 16, 16, 16, float> acc[2][4];
    #pragma unroll
    for (int ti = 0; ti < 2; ti++)
        #pragma unroll
        for (int tj = 0; tj < 4; tj++) wmma::fill_fragment(acc[ti][tj], 0.0f);

    #pragma unroll 2
    for (int ks = 0; ks < 8; ks++) {
        wmma::fragment<wmma::matrix_a, 16, 16, 16, __half, wmma::row_major> ah[2], al[2];
        #pragma unroll
        for (int ti = 0; ti < 2; ti++) {
            int mrow = wm*32 + ti*16;
            wmma::load_matrix_sync(ah[ti], sAh + mrow*LDT + ks*16, LDT);
            wmma::load_matrix_sync(al[ti], sAl + mrow*LDT + ks*16, LDT);
        }
        wmma::fragment<wmma::matrix_b, 16, 16, 16, __half, wmma::col_major> bh[4], bl[4];
        #pragma unroll
        for (int tj = 0; tj < 4; tj++) {
            int nrow = wn*64 + tj*16;
            wmma::load_matrix_sync(bh[tj], sBh + nrow*LDT + ks*16, LDT);
            wmma::load_matrix_sync(bl[tj], sBl + nrow*LDT + ks*16, LDT);
        }
        #pragma unroll
        for (int ti = 0; ti < 2; ti++)
            #pragma unroll
            for (int tj = 0; tj < 4; tj++) {
                wmma::mma_sync(acc[ti][tj], ah[ti], bh[tj], acc[ti][tj]);
                wmma::mma_sync(acc[ti][tj], ah[ti], bl[tj], acc[ti][tj]);
                wmma::mma_sync(acc[ti][tj], al[ti], bh[tj], acc[ti][tj]);
            }
    }
    __syncthreads();

    float* stg = (float*)smem + w*16*20;
    const int r = lane >> 1, seg = lane & 1;
    #pragma unroll 1
    for (int ti = 0; ti < 2; ti++)
    #pragma unroll 1
    for (int tj = 0; tj < 4; tj++) {
        wmma::store_matrix_sync(stg, acc[ti][tj], 20, wmma::mem_row_major);
        __syncwarp();
        size_t orow = (size_t)(m0 + wm*32 + ti*16 + r);
        int nbase = n0 + wn*64 + tj*16 + seg*8;
        float v[8];
        #pragma unroll
        for (int i = 0; i < 8; i++) {
            int n = nbase + i;
            v[i] = stg[r*20 + seg*8 + i] + ((n < Ntot) ? bias[n] : 0.f);
        }
        if (nbase + 8 <= Ntot) {
            *(float4*)(C + orow*ldC + nbase)     = make_float4(v[0],v[1],v[2],v[3]);
            *(float4*)(C + orow*ldC + nbase + 4) = make_float4(v[4],v[5],v[6],v[7]);
        } else {
            for (int i = 0; i < 8; i++)
                if (nbase + i < Ntot) C[orow*ldC + nbase + i] = v[i];
        }
        __syncwarp();
    }
}

// ---------------- LSTM recurrence: 256 threads, 2 gates x 4 batches per thread --------
// A rows are [t*BATCH+b] fp32: per step the grid reads one contiguous 2MB slab.
#define KC 16
#define KR 16
__global__ __launch_bounds__(256) void lstm_kernel(const float* __restrict__ A,
                                                   __half* __restrict__ hsh)
{
    __shared__ float h_s[4][HID];
    __shared__ float c_s[4][HID];
    __shared__ float g_s[4][GATE];
    extern __shared__ float4 Wc[];   // KC*GATE float4 = 128 KB

    const int tid = threadIdx.x;
    const int j0 = tid, j1 = tid + 256;
    const int bb = blockIdx.x * 4;
    const int ub0 = tid >> 7,      uh = tid & 127;
    const int ub1 = 2 + (tid >> 7);

    h_s[ub0][uh] = 0.f; h_s[ub1][uh] = 0.f;
    c_s[ub0][uh] = 0.f; c_s[ub1][uh] = 0.f;

    for (int l = 0; l < NL; l++) {
        const float4* W = g_Wt4 + l*(HID/4)*GATE;
        const float bias0 = g_blstm[l*GATE + j0];
        const float bias1 = g_blstm[l*GATE + j1];
        __syncthreads();
        for (int q = tid; q < KC*GATE; q += 256) Wc[q] = W[q];
        f4u w0[KR], w1[KR];
        #pragma unroll
        for (int r = 0; r < KR; r++) {
            w0[r].f4 = W[(KC+r)*GATE + j0];
            w1[r].f4 = W[(KC+r)*GATE + j1];
        }
        __syncthreads();

        float a0[4], a1[4];
        {
            const float* Ar = A + (size_t)bb*(NL*GATE) + l*GATE;
            #pragma unroll
            for (int b = 0; b < 4; b++) {
                a0[b] = Ar[(size_t)b*(NL*GATE) + j0];
                a1[b] = Ar[(size_t)b*(NL*GATE) + j1];
            }
        }

        for (int t = 0; t < SEQ; t++) {
            float na0[4], na1[4];
            if (t + 1 < SEQ) {
                const float* Arn = A + ((size_t)((t+1)*BATCH + bb))*(NL*GATE) + l*GATE;
                #pragma unroll
                for (int b = 0; b < 4; b++) {
                    na0[b] = Arn[(size_t)b*(NL*GATE) + j0];
                    na1[b] = Arn[(size_t)b*(NL*GATE) + j1];
                }
            } else {
                #pragma unroll
                for (int b = 0; b < 4; b++) { na0[b] = 0.f; na1[b] = 0.f; }
            }

            unsigned long long s0[4] = {0,0,0,0}, s1[4] = {0,0,0,0};
            #pragma unroll
            for (int k4 = 0; k4 < KC; k4++) {
                f4u wv0; wv0.f4 = Wc[k4*GATE + j0];
                f4u wv1; wv1.f4 = Wc[k4*GATE + j1];
                #pragma unroll
                for (int b = 0; b < 4; b++) {
                    f4u hb; hb.f4 = *(const float4*)&h_s[b][k4<<2];
                    ffma2(s0[b], wv0.u[0], hb.u[0]); ffma2(s0[b], wv0.u[1], hb.u[1]);
                    ffma2(s1[b], wv1.u[0], hb.u[0]); ffma2(s1[b], wv1.u[1], hb.u[1]);
                }
            }
            #pragma unroll
            for (int r = 0; r < KR; r++) {
                int k4 = KC + r;
                #pragma unroll
                for (int b = 0; b < 4; b++) {
                    f4u hb; hb.f4 = *(const float4*)&h_s[b][k4<<2];
                    ffma2(s0[b], w0[r].u[0], hb.u[0]); ffma2(s0[b], w0[r].u[1], hb.u[1]);
                    ffma2(s1[b], w1[r].u[0], hb.u[0]); ffma2(s1[b], w1[r].u[1], hb.u[1]);
                }
            }
            #pragma unroll
            for (int b = 0; b < 4; b++) {
                g_s[b][j0] = hadd2(s0[b]) + a0[b] + bias0;
                g_s[b][j1] = hadd2(s1[b]) + a1[b] + bias1;
            }
            __syncthreads();

            #pragma unroll
            for (int p = 0; p < 2; p++) {
                int b = p ? ub1 : ub0;
                float ig = g_s[b][uh];
                float fg = g_s[b][HID   + uh];
                float gg = g_s[b][2*HID + uh];
                float og = g_s[b][3*HID + uh];
                float cc = fsig(fg)*c_s[b][uh] + fsig(ig)*ftanh(gg);
                float hh = fsig(og)*ftanh(cc);
                c_s[b][uh] = cc;
                h_s[b][uh] = hh;
                if (l == NL-1)
                    hsh[((size_t)(bb+b)*SEQ + t)*HID + uh] = __float2half_rn(hh);
            }
            __syncthreads();
            #pragma unroll
            for (int b = 0; b < 4; b++) { a0[b] = na0[b]; a1[b] = na1[b]; }
        }
    }
}

// ---------------- sinkhorn: fused row+col pass, register col sums ---------------------
__global__ __launch_bounds__(512) void sinkhorn_kernel(const float* __restrict__ Min,
                                                       float* __restrict__ out)
{
    extern __shared__ float Ms[];               // SEQ*SEQ
    float* colpart = Ms + SEQ*SEQ;              // 16*SEQ
    float* colinv  = colpart + 16*SEQ;          // SEQ
    const int b = blockIdx.x, tid = threadIdx.x;
    const int lane = tid & 31, w = tid >> 5;    // 16 warps

    const float4* src = (const float4*)(Min + (size_t)b*SEQ*SEQ);
    for (int q = tid; q < SEQ*SEQ/4; q += 512) {
        float4 v = src[q];
        v.x = __expf(v.x); v.y = __expf(v.y); v.z = __expf(v.z); v.w = __expf(v.w);
        ((float4*)Ms)[q] = v;
    }
    if (tid < SEQ) colinv[tid] = 1.0f;
    __syncthreads();

    for (int it = 0; it < 5; it++) {
        float ci[7], cs[7];
        #pragma unroll
        for (int i = 0; i < 7; i++) {
            int c = lane + 32*i;
            ci[i] = (c < SEQ) ? colinv[c] : 0.f;
            cs[i] = 0.f;
        }
        for (int r = w; r < SEQ; r += 16) {
            float v[7]; float s = 0.f;
            #pragma unroll
            for (int i = 0; i < 7; i++) {
                int c = lane + 32*i;
                float x = (c < SEQ) ? Ms[r*SEQ + c] * ci[i] : 0.f;
                v[i] = x; s += x;
            }
            #pragma unroll
            for (int off = 16; off; off >>= 1) s += __shfl_xor_sync(0xffffffffu, s, off);
            float inv = 1.0f / s;
            #pragma unroll
            for (int i = 0; i < 7; i++) {
                int c = lane + 32*i;
                if (c < SEQ) {
                    float x = v[i] * inv;
                    Ms[r*SEQ + c] = x;
                    cs[i] += x;
                }
            }
        }
        #pragma unroll
        for (int i = 0; i < 7; i++) {
            int c = lane + 32*i;
            if (c < SEQ) colpart[w*SEQ + c] = cs[i];
        }
        __syncthreads();
        if (tid < SEQ) {
            float s = 0.f;
            #pragma unroll
            for (int k = 0; k < 16; k++) s += colpart[k*SEQ + tid];
            colinv[tid] = 1.0f / s;
        }
        __syncthreads();
    }

    float4* dst = (float4*)(out + (size_t)b*SEQ*SEQ);
    for (int q = tid; q < SEQ*SEQ/4; q += 512) {
        float4 v = ((const float4*)Ms)[q];
        int c0 = (q % (SEQ/4)) * 4;
        v.x *= colinv[c0]; v.y *= colinv[c0+1]; v.z *= colinv[c0+2]; v.w *= colinv[c0+3];
        dst[q] = v;
    }
}

// ---------------- launch ----------------
extern "C" void kernel_launch(void* const* d_in, const int* in_sizes, int n_in,
                              void* d_out, int out_size)
{
    const float* x     = (const float*)d_in[0];
    const float* w_emb = (const float*)d_in[1];
    const float* b_emb = (const float*)d_in[2];
    const float* w_ih  = (const float*)d_in[3];
    const float* w_hh  = (const float*)d_in[4];
    const float* b_ih  = (const float*)d_in[5];
    const float* b_hh  = (const float*)d_in[6];
    const float* w_fc1 = (const float*)d_in[7];
    const float* b_fc1 = (const float*)d_in[8];
    const float* w_fc2 = (const float*)d_in[9];
    const float* b_fc2 = (const float*)d_in[10];
    float* out = (float*)d_out;

    float *Ab, *Mb, *zero;
    __half *xsh,*wih,*wf1,*wf2h,*wf2l,*hsh,*f1h,*f1l;
    cudaGetSymbolAddress((void**)&Ab,   g_A);
    cudaGetSymbolAddress((void**)&Mb,   g_Mb);
    cudaGetSymbolAddress((void**)&zero, g_zero);
    cudaGetSymbolAddress((void**)&xsh,  g_xsh);
    cudaGetSymbolAddress((void**)&wih,  g_wih);
    cudaGetSymbolAddress((void**)&wf1,  g_wf1);
    cudaGetSymbolAddress((void**)&wf2h, g_wf2h); cudaGetSymbolAddress((void**)&wf2l, g_wf2l);
    cudaGetSymbolAddress((void**)&hsh,  g_hsh);
    cudaGetSymbolAddress((void**)&f1h,  g_f1h);  cudaGetSymbolAddress((void**)&f1l, g_f1l);

    const int TG1_SMEM = 2*128*136*2;         // 69632 (2 tiles -> 2 CTAs/SM)
    const int TG3_SMEM = 4*128*136*2;         // 139264
    const int LS_SMEM  = KC*GATE*16;          // 131072
    const int SK_SMEM  = (SEQ*SEQ + 16*SEQ + SEQ)*4;   // 173600
    cudaFuncSetAttribute(tgemm1_kernel,   cudaFuncAttributeMaxDynamicSharedMemorySize, TG1_SMEM);
    cudaFuncSetAttribute(tgemm3_kernel,   cudaFuncAttributeMaxDynamicSharedMemorySize, TG3_SMEM);
    cudaFuncSetAttribute(lstm_kernel,     cudaFuncAttributeMaxDynamicSharedMemorySize, LS_SMEM);
    cudaFuncSetAttribute(sinkhorn_kernel, cudaFuncAttributeMaxDynamicSharedMemorySize, SK_SMEM);

    // 1) prep: Whh transpose, bias sum, weight conversions
    prep_kernel<<<128, 256>>>(w_hh, b_ih, b_hh, w_ih, w_fc1, w_fc2);
    // 2) embed -> xs fp16 hi, rows [t*BATCH+b]
    embed_kernel<<<dim3(1, MROWS/128), 256, 2*128*(FIN/4)*16>>>(x, w_emb, b_emb, xsh);
    // 3) gemm3: A = xs @ Wih^T, 1-product fp16 (activation rounding already dominates)
    tgemm1_kernel<<<dim3(NL*GATE/128, MROWS/128), 256, TG1_SMEM>>>(
        xsh, wih, zero, Ab, nullptr, nullptr, NL*GATE, NL*GATE, NL*GATE, 0);
    // 4) LSTM recurrence -> hs fp16 hi (rows [b*SEQ+t])
    lstm_kernel<<<BATCH/4, 256, LS_SMEM>>>(Ab, hsh);
    // 5) fc1 (leaky) -> f1 fp16 split (exact split of fp32 result; fc2 3-product reads it)
    tgemm1_kernel<<<dim3(1, MROWS/128), 256, TG1_SMEM>>>(
        hsh, wf1, b_fc1, nullptr, f1h, f1l, EMB, EMB, EMB, 1);
    // 6) fc2 -> M fp32, 3-product (output path)
    tgemm3_kernel<<<dim3(2, MROWS/128), 256, TG3_SMEM>>>(
        f1h, f1l, wf2h, wf2l, b_fc2, Mb, SEQ, SEQ, SEQ);
    // 7) sinkhorn (fused row+col passes)
    sinkhorn_kernel<<<BATCH, 512, SK_SMEM>>>(Mb, out);
}

// round 16
// speedup vs baseline: 1.6279x; 1.3579x over previous
#include <cuda_runtime.h>
#include <cuda_fp16.h>
#include <mma.h>
#include <math.h>
#include <stdint.h>

#define BATCH 512
#define SEQ   200
#define FIN   32
#define EMB   128
#define HID   128
#define GATE  512            // 4*HID
#define NL    2
#define MROWS (BATCH*SEQ)    // 102400
#define KDIM  128

// ---------------- scratch (__device__ globals) ----------------
__device__ float  g_A [(size_t)MROWS*NL*GATE];          // LSTM input projections (fp32), [t][b] rows
__device__ float  g_Mb[(size_t)MROWS*SEQ];              // fc2 out [b][n][n']
__device__ float  g_blstm[NL*GATE];                     // b_ih + b_hh
__device__ float  g_zero[NL*GATE];                      // zero bias for gemm3

// fp16 operands
__device__ __half g_whh16[NL*GATE*HID];                 // Whh fp16 [l][gate][k]
__device__ __half g_xsh[(size_t)MROWS*EMB];                             // [t][b] rows
__device__ __half g_wih [NL*GATE*EMB];
__device__ __half g_wf1 [EMB*HID];
__device__ __half g_wf2h[SEQ*EMB],          g_wf2l[SEQ*EMB];
__device__ __half g_hsh[(size_t)MROWS*HID];                             // [b][t] rows
__device__ __half g_f1h[(size_t)MROWS*EMB], g_f1l[(size_t)MROWS*EMB];

__device__ __forceinline__ void split2h(float v, __half& h, __half& l) {
    h = __float2half_rn(v);
    l = __float2half_rn(v - __half2float(h));
}

// packed fp32x2 FMA (embed)
union f4u { float4 f4; unsigned long long u[2]; };
__device__ __forceinline__ void ffma2(unsigned long long& d,
                                      unsigned long long a,
                                      unsigned long long b) {
    asm("fma.rn.f32x2 %0, %1, %2, %0;" : "+l"(d) : "l"(a), "l"(b));
}
__device__ __forceinline__ float hadd2(unsigned long long v) {
    union { unsigned long long u; float2 f; } c; c.u = v;
    return c.f.x + c.f.y;
}

// fast activations (MUFU-based)
__device__ __forceinline__ float fsig(float x)  { return __fdividef(1.f, 1.f + __expf(-x)); }
__device__ __forceinline__ float ftanh(float x) { return __fdividef(2.f, 1.f + __expf(-2.f*x)) - 1.f; }

// ---------------- prep: bias sums, weight fp16 conversions ----------------
__global__ void prep_kernel(const float* __restrict__ w_hh,
                            const float* __restrict__ b_ih,
                            const float* __restrict__ b_hh,
                            const float* __restrict__ w_ih,
                            const float* __restrict__ w_fc1,
                            const float* __restrict__ w_fc2) {
    int idx = blockIdx.x*blockDim.x + threadIdx.x;
    int stride = gridDim.x*blockDim.x;
    for (int q = idx; q < NL*GATE*HID; q += stride) g_whh16[q] = __float2half_rn(w_hh[q]);
    for (int q = idx; q < NL*GATE; q += stride) {
        g_blstm[q] = b_ih[q] + b_hh[q];
        g_zero[q]  = 0.f;
    }
    for (int q = idx; q < NL*GATE*EMB; q += stride) g_wih[q] = __float2half_rn(w_ih[q]);
    for (int q = idx; q < EMB*HID;     q += stride) g_wf1[q] = __float2half_rn(w_fc1[q]);
    for (int q = idx; q < SEQ*EMB;     q += stride) split2h(w_fc2[q], g_wf2h[q], g_wf2l[q]);
}

// ---------------- embed: e = leaky(x @ w_emb^T + b) -> fp16 hi, rows [t*BATCH+b] -------
__global__ __launch_bounds__(256) void embed_kernel(
    const float* __restrict__ A, const float* __restrict__ B,
    const float* __restrict__ bias,
    __half* __restrict__ outh)
{
    const int K = FIN, K4 = FIN/4, N = EMB;
    extern __shared__ float4 sm4[];
    float4* As4 = sm4;
    float4* Bs4 = sm4 + 128*K4;

    const int m0 = blockIdx.y * 128;
    const int tid = threadIdx.x;

    for (int q = tid; q < 128*K4; q += 256) {
        int row = q / K4, k4 = q % K4;
        As4[row*K4 + (k4 ^ ((row>>3)&7))] = *(const float4*)(A + ((size_t)(m0+row))*K + (k4<<2));
    }
    for (int q = tid; q < 128*K4; q += 256) {
        int row = q / K4, k4 = q % K4;
        Bs4[row*K4 + (k4 ^ ((row>>3)&7))] = *(const float4*)(B + ((size_t)row)*K + (k4<<2));
    }
    __syncthreads();

    const int tx = tid & 15, ty = tid >> 4;
    const int swa = ty & 7, swb = tx & 7;

    unsigned long long acc[8][8];
    #pragma unroll
    for (int i = 0; i < 8; i++)
        #pragma unroll
        for (int j = 0; j < 8; j++) acc[i][j] = 0ULL;

    for (int k4 = 0; k4 < K4; k4++) {
        int ka = (k4 ^ swa) & (K4-1), kb = (k4 ^ swb) & (K4-1);
        f4u av[8];
        #pragma unroll
        for (int ii = 0; ii < 8; ii++) av[ii].f4 = As4[(ty*8+ii)*K4 + ka];
        #pragma unroll
        for (int jj = 0; jj < 8; jj++) {
            f4u bv; bv.f4 = Bs4[(tx*8+jj)*K4 + kb];
            #pragma unroll
            for (int ii = 0; ii < 8; ii++) {
                ffma2(acc[ii][jj], av[ii].u[0], bv.u[0]);
                ffma2(acc[ii][jj], av[ii].u[1], bv.u[1]);
            }
        }
    }

    #pragma unroll
    for (int ii = 0; ii < 8; ii++) {
        int m = m0 + ty*8 + ii;
        int b = m / SEQ, t = m - b*SEQ;
        size_t orow = (size_t)t*BATCH + b;     // [t][b] row remap for gemm3/lstm locality
        union { unsigned short s[8]; uint4 v; } ph;
        #pragma unroll
        for (int jj = 0; jj < 8; jj++) {
            int n = tx*8 + jj;
            float v = hadd2(acc[ii][jj]) + bias[n];
            v = (v >= 0.f) ? v : 0.01f*v;
            ph.s[jj] = __half_as_ushort(__float2half_rn(v));
        }
        *(uint4*)(outh + orow*N + tx*8) = ph.v;
    }
}

// ---------------- tgemm1: C = act(A @ B^T + bias), plain fp16, fp32 acc ---------------
__global__ __launch_bounds__(256, 2) void tgemm1_kernel(
    const __half* __restrict__ Ah, const __half* __restrict__ Bh,
    const float* __restrict__ bias, float* __restrict__ C,
    __half* __restrict__ Ch, __half* __restrict__ Cl,
    int Ntot, int ldC, int Brows, int act)
{
    using namespace nvcuda;
    const int LDT = 136;
    extern __shared__ __align__(32) char smem[];
    __half* sAh = (__half*)smem;
    __half* sBh = sAh + 128*LDT;

    const int tid = threadIdx.x;
    const int w = tid >> 5, lane = tid & 31;
    const int wm = w >> 1, wn = w & 1;          // 4x2 warp grid
    const int m0 = blockIdx.y * 128;
    const int n0 = blockIdx.x * 128;

    for (int q = tid; q < 128*16; q += 256) {
        int row = q >> 4, c = q & 15;
        uint4 va  = *(const uint4*)(Ah + (size_t)(m0+row)*KDIM + c*8);
        uint4 vb  = make_uint4(0u,0u,0u,0u);
        if (n0 + row < Brows)
            vb = *(const uint4*)(Bh + (size_t)(n0+row)*KDIM + c*8);
        *(uint4*)(sAh + row*LDT + c*8) = va;
        *(uint4*)(sBh + row*LDT + c*8) = vb;
    }
    __syncthreads();

    wmma::fragment<wmma::accumulator, 16, 16, 16, float> acc[2][4];
    #pragma unroll
    for (int ti = 0; ti < 2; ti++)
        #pragma unroll
        for (int tj = 0; tj < 4; tj++) wmma::fill_fragment(acc[ti][tj], 0.0f);

    #pragma unroll 2
    for (int ks = 0; ks < 8; ks++) {
        wmma::fragment<wmma::matrix_a, 16, 16, 16, __half, wmma::row_major> ah[2];
        #pragma unroll
        for (int ti = 0; ti < 2; ti++)
            wmma::load_matrix_sync(ah[ti], sAh + (wm*32 + ti*16)*LDT + ks*16, LDT);
        #pragma unroll
        for (int tj = 0; tj < 4; tj++) {
            int nrow = wn*64 + tj*16;
            wmma::fragment<wmma::matrix_b, 16, 16, 16, __half, wmma::col_major> bh;
            wmma::load_matrix_sync(bh, sBh + nrow*LDT + ks*16, LDT);
            #pragma unroll
            for (int ti = 0; ti < 2; ti++)
                wmma::mma_sync(acc[ti][tj], ah[ti], bh, acc[ti][tj]);
        }
    }
    __syncthreads();   // tiles dead; reuse smem front as per-warp stage

    float* stg = (float*)smem + w*16*20;
    const int r = lane >> 1, seg = lane & 1;
    #pragma unroll 1
    for (int ti = 0; ti < 2; ti++)
    #pragma unroll 1
    for (int tj = 0; tj < 4; tj++) {
        wmma::store_matrix_sync(stg, acc[ti][tj], 20, wmma::mem_row_major);
        __syncwarp();
        size_t orow = (size_t)(m0 + wm*32 + ti*16 + r);
        int nbase = n0 + wn*64 + tj*16 + seg*8;
        float v[8];
        #pragma unroll
        for (int i = 0; i < 8; i++) {
            int n = nbase + i;
            float t = stg[r*20 + seg*8 + i] + ((n < Ntot) ? bias[n] : 0.f);
            if (act) t = (t >= 0.f) ? t : 0.01f*t;
            v[i] = t;
        }
        if (C) {
            if (nbase + 8 <= Ntot) {
                *(float4*)(C + orow*ldC + nbase)     = make_float4(v[0],v[1],v[2],v[3]);
                *(float4*)(C + orow*ldC + nbase + 4) = make_float4(v[4],v[5],v[6],v[7]);
            } else {
                for (int i = 0; i < 8; i++)
                    if (nbase + i < Ntot) C[orow*ldC + nbase + i] = v[i];
            }
        } else {
            union { unsigned short s[8]; uint4 q; } ph, pl;
            #pragma unroll
            for (int i = 0; i < 8; i++) {
                __half h, l; split2h(v[i], h, l);
                ph.s[i] = __half_as_ushort(h);
                pl.s[i] = __half_as_ushort(l);
            }
            *(uint4*)(Ch + orow*ldC + nbase) = ph.q;
            *(uint4*)(Cl + orow*ldC + nbase) = pl.q;
        }
        __syncwarp();
    }
}

// ---------------- tgemm3: C = (Ah+Al) @ (Bh+Bl)^T + bias (3-product, output path) -----
__global__ __launch_bounds__(256) void tgemm3_kernel(
    const __half* __restrict__ Ah, const __half* __restrict__ Al,
    const __half* __restrict__ Bh, const __half* __restrict__ Bl,
    const float* __restrict__ bias, float* __restrict__ C,
    int Ntot, int ldC, int Brows)
{
    using namespace nvcuda;
    const int LDT = 136;
    extern __shared__ __align__(32) char smem[];
    __half* sAh = (__half*)smem;
    __half* sAl = sAh + 128*LDT;
    __half* sBh = sAl + 128*LDT;
    __half* sBl = sBh + 128*LDT;

    const int tid = threadIdx.x;
    const int w = tid >> 5, lane = tid & 31;
    const int wm = w >> 1, wn = w & 1;
    const int m0 = blockIdx.y * 128;
    const int n0 = blockIdx.x * 128;

    for (int q = tid; q < 128*16; q += 256) {
        int row = q >> 4, c = q & 15;
        uint4 va  = *(const uint4*)(Ah + (size_t)(m0+row)*KDIM + c*8);
        uint4 val = *(const uint4*)(Al + (size_t)(m0+row)*KDIM + c*8);
        uint4 vb  = make_uint4(0u,0u,0u,0u), vbl = make_uint4(0u,0u,0u,0u);
        if (n0 + row < Brows) {
            vb  = *(const uint4*)(Bh + (size_t)(n0+row)*KDIM + c*8);
            vbl = *(const uint4*)(Bl + (size_t)(n0+row)*KDIM + c*8);
        }
        *(uint4*)(sAh + row*LDT + c*8) = va;
        *(uint4*)(sAl + row*LDT + c*8) = val;
        *(uint4*)(sBh + row*LDT + c*8) = vb;
        *(uint4*)(sBl + row*LDT + c*8) = vbl;
    }
    __syncthreads();

    wmma::fragment<wmma::accumulator, 16, 16, 16, float> acc[2][4];
    #pragma unroll
    for (int ti = 0; ti < 2; ti++)
        #pragma unroll
        for (int tj = 0; tj < 4; tj++) wmma::fill_fragment(acc[ti][tj], 0.0f);

    #pragma unroll 2
    for (int ks = 0; ks < 8; ks++) {
        wmma::fragment<wmma::matrix_a, 16, 16, 16, __half, wmma::row_major> ah[2], al[2];
        #pragma unroll
        for (int ti = 0; ti < 2; ti++) {
            int mrow = wm*32 + ti*16;
            wmma::load_matrix_sync(ah[ti], sAh + mrow*LDT + ks*16, LDT);
            wmma::load_matrix_sync(al[ti], sAl + mrow*LDT + ks*16, LDT);
        }
        wmma::fragment<wmma::matrix_b, 16, 16, 16, __half, wmma::col_major> bh[4], bl[4];
        #pragma unroll
        for (int tj = 0; tj < 4; tj++) {
            int nrow = wn*64 + tj*16;
            wmma::load_matrix_sync(bh[tj], sBh + nrow*LDT + ks*16, LDT);
            wmma::load_matrix_sync(bl[tj], sBl + nrow*LDT + ks*16, LDT);
        }
        #pragma unroll
        for (int ti = 0; ti < 2; ti++)
            #pragma unroll
            for (int tj = 0; tj < 4; tj++) {
                wmma::mma_sync(acc[ti][tj], ah[ti], bh[tj], acc[ti][tj]);
                wmma::mma_sync(acc[ti][tj], ah[ti], bl[tj], acc[ti][tj]);
                wmma::mma_sync(acc[ti][tj], al[ti], bh[tj], acc[ti][tj]);
            }
    }
    __syncthreads();

    float* stg = (float*)smem + w*16*20;
    const int r = lane >> 1, seg = lane & 1;
    #pragma unroll 1
    for (int ti = 0; ti < 2; ti++)
    #pragma unroll 1
    for (int tj = 0; tj < 4; tj++) {
        wmma::store_matrix_sync(stg, acc[ti][tj], 20, wmma::mem_row_major);
        __syncwarp();
        size_t orow = (size_t)(m0 + wm*32 + ti*16 + r);
        int nbase = n0 + wn*64 + tj*16 + seg*8;
        float v[8];
        #pragma unroll
        for (int i = 0; i < 8; i++) {
            int n = nbase + i;
            v[i] = stg[r*20 + seg*8 + i] + ((n < Ntot) ? bias[n] : 0.f);
        }
        if (nbase + 8 <= Ntot) {
            *(float4*)(C + orow*ldC + nbase)     = make_float4(v[0],v[1],v[2],v[3]);
            *(float4*)(C + orow*ldC + nbase + 4) = make_float4(v[4],v[5],v[6],v[7]);
        } else {
            for (int i = 0; i < 8; i++)
                if (nbase + i < Ntot) C[orow*ldC + nbase + i] = v[i];
        }
        __syncwarp();
    }
}

// ---------------- LSTM recurrence: tensor-core (m32n8k16), W register-resident --------
// 128 CTAs x 4 batches. Warp w owns gates [64w,64w+64): 2 m-tiles x 8 k-tiles of W frags.
// h in smem fp16 [8][LDH] (batches 4..7 zero-padded). c-state in registers.
#define LDW  136
#define LDH  136
#define LDSG 12
__global__ __launch_bounds__(256) void lstm_kernel(const float* __restrict__ A,
                                                   const __half* __restrict__ Whh16,
                                                   __half* __restrict__ hsh)
{
    using namespace nvcuda;
    extern __shared__ __align__(32) char dsm[];
    __half* sW = (__half*)dsm;                    // 512*LDW halves = 139264 B
    __shared__ __half h16[8*LDH];
    __shared__ float  stage[GATE*LDSG];           // 24576 B

    const int tid = threadIdx.x;
    const int w = tid >> 5;
    const int bb = blockIdx.x * 4;
    const int ub0 = tid >> 7, uh = tid & 127;
    const int ub1 = 2 + ub0;

    for (int q = tid; q < 8*LDH; q += 256) h16[q] = __float2half_rn(0.f);
    float c0 = 0.f, c1 = 0.f;

    for (int l = 0; l < NL; l++) {
        // stage this layer's Whh (fp16) and lift into register fragments
        __syncthreads();
        const __half* Wg = Whh16 + (size_t)l*GATE*HID;
        for (int q = tid; q < GATE*16; q += 256) {
            int row = q >> 4, c = q & 15;
            *(uint4*)(sW + row*LDW + c*8) = *(const uint4*)(Wg + (size_t)row*HID + c*8);
        }
        __syncthreads();

        wmma::fragment<wmma::matrix_a, 32, 8, 16, __half, wmma::row_major> aW[2][8];
        #pragma unroll
        for (int mt = 0; mt < 2; mt++)
            #pragma unroll
            for (int kt = 0; kt < 8; kt++)
                wmma::load_matrix_sync(aW[mt][kt], sW + (w*64 + mt*32)*LDW + kt*16, LDW);

        float bias_q[4];
        #pragma unroll
        for (int q = 0; q < 4; q++) bias_q[q] = g_blstm[l*GATE + q*HID + uh];

        // prefetch A for t=0 (update-phase mapping; coalesced 128B per (b,q))
        float a0[4], a1[4];
        {
            const float* Ar = A + (size_t)bb*(NL*GATE) + l*GATE;
            #pragma unroll
            for (int q = 0; q < 4; q++) {
                a0[q] = Ar[(size_t)ub0*(NL*GATE) + q*HID + uh];
                a1[q] = Ar[(size_t)ub1*(NL*GATE) + q*HID + uh];
            }
        }

        for (int t = 0; t < SEQ; t++) {
            // ---- MMA phase: gates = Whh @ h ----
            wmma::fragment<wmma::accumulator, 32, 8, 16, float> acc[2];
            wmma::fill_fragment(acc[0], 0.0f);
            wmma::fill_fragment(acc[1], 0.0f);
            #pragma unroll
            for (int kt = 0; kt < 8; kt++) {
                wmma::fragment<wmma::matrix_b, 32, 8, 16, __half, wmma::col_major> bh;
                wmma::load_matrix_sync(bh, h16 + kt*16, LDH);
                wmma::mma_sync(acc[0], aW[0][kt], bh, acc[0]);
                wmma::mma_sync(acc[1], aW[1][kt], bh, acc[1]);
            }
            wmma::store_matrix_sync(stage + (w*64 +  0)*LDSG, acc[0], LDSG, wmma::mem_row_major);
            wmma::store_matrix_sync(stage + (w*64 + 32)*LDSG, acc[1], LDSG, wmma::mem_row_major);
            __syncthreads();

            // ---- update phase ----
            float na0[4], na1[4];
            if (t + 1 < SEQ) {
                const float* Arn = A + ((size_t)((t+1)*BATCH + bb))*(NL*GATE) + l*GATE;
                #pragma unroll
                for (int q = 0; q < 4; q++) {
                    na0[q] = Arn[(size_t)ub0*(NL*GATE) + q*HID + uh];
                    na1[q] = Arn[(size_t)ub1*(NL*GATE) + q*HID + uh];
                }
            } else {
                #pragma unroll
                for (int q = 0; q < 4; q++) { na0[q] = 0.f; na1[q] = 0.f; }
            }

            {
                float ig = stage[(0*HID+uh)*LDSG + ub0] + a0[0] + bias_q[0];
                float fg = stage[(1*HID+uh)*LDSG + ub0] + a0[1] + bias_q[1];
                float gg = stage[(2*HID+uh)*LDSG + ub0] + a0[2] + bias_q[2];
                float og = stage[(3*HID+uh)*LDSG + ub0] + a0[3] + bias_q[3];
                float cc = fsig(fg)*c0 + fsig(ig)*ftanh(gg);
                float hh = fsig(og)*ftanh(cc);
                c0 = cc;
                h16[ub0*LDH + uh] = __float2half_rn(hh);
                if (l == NL-1)
                    hsh[((size_t)(bb+ub0)*SEQ + t)*HID + uh] = __float2half_rn(hh);
            }
            {
                float ig = stage[(0*HID+uh)*LDSG + ub1] + a1[0] + bias_q[0];
                float fg = stage[(1*HID+uh)*LDSG + ub1] + a1[1] + bias_q[1];
                float gg = stage[(2*HID+uh)*LDSG + ub1] + a1[2] + bias_q[2];
                float og = stage[(3*HID+uh)*LDSG + ub1] + a1[3] + bias_q[3];
                float cc = fsig(fg)*c1 + fsig(ig)*ftanh(gg);
                float hh = fsig(og)*ftanh(cc);
                c1 = cc;
                h16[ub1*LDH + uh] = __float2half_rn(hh);
                if (l == NL-1)
                    hsh[((size_t)(bb+ub1)*SEQ + t)*HID + uh] = __float2half_rn(hh);
            }
            __syncthreads();
            #pragma unroll
            for (int q = 0; q < 4; q++) { a0[q] = na0[q]; a1[q] = na1[q]; }
        }
    }
}

// ---------------- sinkhorn: fused row+col pass, register col sums ---------------------
__global__ __launch_bounds__(512) void sinkhorn_kernel(const float* __restrict__ Min,
                                                       float* __restrict__ out)
{
    extern __shared__ float Ms[];               // SEQ*SEQ
    float* colpart = Ms + SEQ*SEQ;              // 16*SEQ
    float* colinv  = colpart + 16*SEQ;          // SEQ
    const int b = blockIdx.x, tid = threadIdx.x;
    const int lane = tid & 31, w = tid >> 5;    // 16 warps

    const float4* src = (const float4*)(Min + (size_t)b*SEQ*SEQ);
    for (int q = tid; q < SEQ*SEQ/4; q += 512) {
        float4 v = src[q];
        v.x = __expf(v.x); v.y = __expf(v.y); v.z = __expf(v.z); v.w = __expf(v.w);
        ((float4*)Ms)[q] = v;
    }
    if (tid < SEQ) colinv[tid] = 1.0f;
    __syncthreads();

    for (int it = 0; it < 5; it++) {
        float ci[7], cs[7];
        #pragma unroll
        for (int i = 0; i < 7; i++) {
            int c = lane + 32*i;
            ci[i] = (c < SEQ) ? colinv[c] : 0.f;
            cs[i] = 0.f;
        }
        for (int r = w; r < SEQ; r += 16) {
            float v[7]; float s = 0.f;
            #pragma unroll
            for (int i = 0; i < 7; i++) {
                int c = lane + 32*i;
                float x = (c < SEQ) ? Ms[r*SEQ + c] * ci[i] : 0.f;
                v[i] = x; s += x;
            }
            #pragma unroll
            for (int off = 16; off; off >>= 1) s += __shfl_xor_sync(0xffffffffu, s, off);
            float inv = 1.0f / s;
            #pragma unroll
            for (int i = 0; i < 7; i++) {
                int c = lane + 32*i;
                if (c < SEQ) {
                    float x = v[i] * inv;
                    Ms[r*SEQ + c] = x;
                    cs[i] += x;
                }
            }
        }
        #pragma unroll
        for (int i = 0; i < 7; i++) {
            int c = lane + 32*i;
            if (c < SEQ) colpart[w*SEQ + c] = cs[i];
        }
        __syncthreads();
        if (tid < SEQ) {
            float s = 0.f;
            #pragma unroll
            for (int k = 0; k < 16; k++) s += colpart[k*SEQ + tid];
            colinv[tid] = 1.0f / s;
        }
        __syncthreads();
    }

    float4* dst = (float4*)(out + (size_t)b*SEQ*SEQ);
    for (int q = tid; q < SEQ*SEQ/4; q += 512) {
        float4 v = ((const float4*)Ms)[q];
        int c0 = (q % (SEQ/4)) * 4;
        v.x *= colinv[c0]; v.y *= colinv[c0+1]; v.z *= colinv[c0+2]; v.w *= colinv[c0+3];
        dst[q] = v;
    }
}

// ---------------- launch ----------------
extern "C" void kernel_launch(void* const* d_in, const int* in_sizes, int n_in,
                              void* d_out, int out_size)
{
    const float* x     = (const float*)d_in[0];
    const float* w_emb = (const float*)d_in[1];
    const float* b_emb = (const float*)d_in[2];
    const float* w_ih  = (const float*)d_in[3];
    const float* w_hh  = (const float*)d_in[4];
    const float* b_ih  = (const float*)d_in[5];
    const float* b_hh  = (const float*)d_in[6];
    const float* w_fc1 = (const float*)d_in[7];
    const float* b_fc1 = (const float*)d_in[8];
    const float* w_fc2 = (const float*)d_in[9];
    const float* b_fc2 = (const float*)d_in[10];
    float* out = (float*)d_out;

    float *Ab, *Mb, *zero;
    __half *whh16,*xsh,*wih,*wf1,*wf2h,*wf2l,*hsh,*f1h,*f1l;
    cudaGetSymbolAddress((void**)&Ab,    g_A);
    cudaGetSymbolAddress((void**)&Mb,    g_Mb);
    cudaGetSymbolAddress((void**)&zero,  g_zero);
    cudaGetSymbolAddress((void**)&whh16, g_whh16);
    cudaGetSymbolAddress((void**)&xsh,   g_xsh);
    cudaGetSymbolAddress((void**)&wih,   g_wih);
    cudaGetSymbolAddress((void**)&wf1,   g_wf1);
    cudaGetSymbolAddress((void**)&wf2h,  g_wf2h); cudaGetSymbolAddress((void**)&wf2l, g_wf2l);
    cudaGetSymbolAddress((void**)&hsh,   g_hsh);
    cudaGetSymbolAddress((void**)&f1h,   g_f1h);  cudaGetSymbolAddress((void**)&f1l, g_f1l);

    const int TG1_SMEM = 2*128*136*2;         // 69632 (2 tiles -> 2 CTAs/SM)
    const int TG3_SMEM = 4*128*136*2;         // 139264
    const int LS_SMEM  = GATE*LDW*2;          // 139264 (fp16 Whh layer tile)
    const int SK_SMEM  = (SEQ*SEQ + 16*SEQ + SEQ)*4;   // 173600
    cudaFuncSetAttribute(tgemm1_kernel,   cudaFuncAttributeMaxDynamicSharedMemorySize, TG1_SMEM);
    cudaFuncSetAttribute(tgemm3_kernel,   cudaFuncAttributeMaxDynamicSharedMemorySize, TG3_SMEM);
    cudaFuncSetAttribute(lstm_kernel,     cudaFuncAttributeMaxDynamicSharedMemorySize, LS_SMEM);
    cudaFuncSetAttribute(sinkhorn_kernel, cudaFuncAttributeMaxDynamicSharedMemorySize, SK_SMEM);

    // 1) prep: bias sum, weight conversions
    prep_kernel<<<128, 256>>>(w_hh, b_ih, b_hh, w_ih, w_fc1, w_fc2);
    // 2) embed -> xs fp16 hi, rows [t*BATCH+b]
    embed_kernel<<<dim3(1, MROWS/128), 256, 2*128*(FIN/4)*16>>>(x, w_emb, b_emb, xsh);
    // 3) gemm3: A = xs @ Wih^T, 1-product fp16, fp32 out
    tgemm1_kernel<<<dim3(NL*GATE/128, MROWS/128), 256, TG1_SMEM>>>(
        xsh, wih, zero, Ab, nullptr, nullptr, NL*GATE, NL*GATE, NL*GATE, 0);
    // 4) LSTM recurrence (tensor-core) -> hs fp16 (rows [b*SEQ+t])
    lstm_kernel<<<BATCH/4, 256, LS_SMEM>>>(Ab, whh16, hsh);
    // 5) fc1 (leaky) -> f1 fp16 split, 1-product
    tgemm1_kernel<<<dim3(1, MROWS/128), 256, TG1_SMEM>>>(
        hsh, wf1, b_fc1, nullptr, f1h, f1l, EMB, EMB, EMB, 1);
    // 6) fc2 -> M fp32, 3-product (output path)
    tgemm3_kernel<<<dim3(2, MROWS/128), 256, TG3_SMEM>>>(
        f1h, f1l, wf2h, wf2l, b_fc2, Mb, SEQ, SEQ, SEQ);
    // 7) sinkhorn (fused row+col passes)
    sinkhorn_kernel<<<BATCH, 512, SK_SMEM>>>(Mb, out);
}